// round 1
// baseline (speedup 1.0000x reference)
#include <cuda_runtime.h>
#include <cuda_bf16.h>
#include <math.h>

#define DIM_ 2048
#define SEQ_ 2048
#define BATCH_ 2
#define NHEADS_ 16
#define NKV_ 4
#define HD_ 128
#define M_ (BATCH_ * SEQ_)   // 4096

// ---------------- scratch (no allocations allowed) ----------------
__device__ float g_q[(size_t)M_ * DIM_];          // 4096 x 2048
__device__ float g_k[(size_t)M_ * (NKV_ * HD_)];  // 4096 x 512
__device__ float g_v[(size_t)M_ * (NKV_ * HD_)];  // 4096 x 512
__device__ float g_attn[(size_t)M_ * DIM_];       // 4096 x 2048

// ---------------- SGEMM: C[M,N] = A[M,K] @ B[K,N], row-major, fp32 ----------------
// BM=128, BN=128, BK=8, 256 threads, 8x8 per thread. Dims must be multiples (they are).
__global__ __launch_bounds__(256) void sgemm_kernel(const float* __restrict__ A,
                                                    const float* __restrict__ B,
                                                    float* __restrict__ C,
                                                    int M, int N, int K) {
    __shared__ float As[8][128];
    __shared__ float Bs[8][128];

    const int tid = threadIdx.x;
    const int bm = blockIdx.y * 128;
    const int bn = blockIdx.x * 128;

    // A tile load: 128x8 = 256 float4 -> 1 per thread
    const int arow = tid >> 1;            // 0..127
    const int acol = (tid & 1) * 4;       // 0 or 4
    // B tile load: 8x128 = 256 float4 -> 1 per thread
    const int brow = tid >> 5;            // 0..7
    const int bcol = (tid & 31) * 4;      // 0..124

    const int tr = (tid >> 4) * 8;        // 0..120
    const int tc = (tid & 15) * 8;        // 0..120

    float acc[8][8];
#pragma unroll
    for (int i = 0; i < 8; i++)
#pragma unroll
        for (int j = 0; j < 8; j++) acc[i][j] = 0.f;

    for (int k0 = 0; k0 < K; k0 += 8) {
        float4 a4 = *(const float4*)(A + (size_t)(bm + arow) * K + k0 + acol);
        As[acol + 0][arow] = a4.x;
        As[acol + 1][arow] = a4.y;
        As[acol + 2][arow] = a4.z;
        As[acol + 3][arow] = a4.w;
        float4 b4 = *(const float4*)(B + (size_t)(k0 + brow) * N + bn + bcol);
        *(float4*)&Bs[brow][bcol] = b4;
        __syncthreads();

#pragma unroll
        for (int kk = 0; kk < 8; kk++) {
            float ra[8], rb[8];
#pragma unroll
            for (int i = 0; i < 8; i++) ra[i] = As[kk][tr + i];
#pragma unroll
            for (int j = 0; j < 8; j++) rb[j] = Bs[kk][tc + j];
#pragma unroll
            for (int i = 0; i < 8; i++)
#pragma unroll
                for (int j = 0; j < 8; j++) acc[i][j] = fmaf(ra[i], rb[j], acc[i][j]);
        }
        __syncthreads();
    }

#pragma unroll
    for (int i = 0; i < 8; i++) {
        float* crow = C + (size_t)(bm + tr + i) * N + bn + tc;
#pragma unroll
        for (int j = 0; j < 8; j += 4) {
            float4 o4 = make_float4(acc[i][j], acc[i][j + 1], acc[i][j + 2], acc[i][j + 3]);
            *(float4*)(crow + j) = o4;
        }
    }
}

// ---------------- RoPE: interleaved pairs, per (b, s, h, i<64) ----------------
__global__ void rope_kernel(float* __restrict__ q, const float* __restrict__ cosf,
                            const float* __restrict__ sinf, int nheads) {
    int idx = blockIdx.x * blockDim.x + threadIdx.x;
    int total = BATCH_ * SEQ_ * nheads * 64;
    if (idx >= total) return;
    int i = idx & 63;
    int h = (idx >> 6) % nheads;
    int s = (idx / (64 * nheads)) % SEQ_;
    int b = idx / (64 * nheads * SEQ_);
    float c = cosf[s * 64 + i];
    float sn = sinf[s * 64 + i];
    float* p = q + ((size_t)(b * SEQ_ + s)) * (nheads * HD_) + h * HD_ + 2 * i;
    float xr = p[0], xi = p[1];
    p[0] = xr * c - xi * sn;
    p[1] = xr * sn + xi * c;
}

// ---------------- Flash-style causal GQA attention ----------------
// Block: 256 threads = 8 warps, 1 warp per q row. Grid: (SEQ/8, NHEADS, BATCH).
__global__ __launch_bounds__(256) void attn_kernel(const float* __restrict__ Q,
                                                   const float* __restrict__ K,
                                                   const float* __restrict__ V,
                                                   float* __restrict__ O) {
    __shared__ float Qs[8][128];
    __shared__ float Ks[128 * 33];   // transposed [d][key], pad 33
    __shared__ float Vs[32 * 128];   // [key][d]

    const int w = threadIdx.x >> 5;
    const int lane = threadIdx.x & 31;
    const int b = blockIdx.z;
    const int h = blockIdx.y;
    const int g = h / (NHEADS_ / NKV_);   // kv head
    const int q0 = blockIdx.x * 8;
    const int qrow = q0 + w;

    const float scale = 0.08838834764831845f;  // 1/sqrt(128)

    const float* qptr = Q + (size_t)(b * SEQ_ + qrow) * DIM_ + h * HD_;
#pragma unroll
    for (int t = lane; t < 128; t += 32) Qs[w][t] = qptr[t] * scale;

    float m = -1e30f, l = 0.f;
    float acc0 = 0.f, acc1 = 0.f, acc2 = 0.f, acc3 = 0.f;

    const float* kbase = K + (size_t)b * SEQ_ * (NKV_ * HD_) + g * HD_;
    const float* vbase = V + (size_t)b * SEQ_ * (NKV_ * HD_) + g * HD_;

    const int nchunk = (q0 + 7) / 32 + 1;
    for (int kb = 0; kb < nchunk; kb++) {
        __syncthreads();
        // stage 32 keys (K transposed, V direct)
        for (int idx = threadIdx.x; idx < 32 * 128; idx += 256) {
            int key = idx >> 7;
            int d = idx & 127;
            size_t goff = (size_t)(kb * 32 + key) * (NKV_ * HD_) + d;
            Ks[d * 33 + key] = kbase[goff];
            Vs[key * 128 + d] = vbase[goff];
        }
        __syncthreads();

        if (kb * 32 <= qrow) {
            const int kglob = kb * 32 + lane;
            float s = 0.f;
#pragma unroll 8
            for (int d = 0; d < 128; d++) s = fmaf(Qs[w][d], Ks[d * 33 + lane], s);
            if (kglob > qrow) s = -1e30f;

            float mx = s;
#pragma unroll
            for (int o = 16; o > 0; o >>= 1) mx = fmaxf(mx, __shfl_xor_sync(0xffffffffu, mx, o));
            float m_new = fmaxf(m, mx);
            float alpha = __expf(m - m_new);
            float p = __expf(s - m_new);
            float ps = p;
#pragma unroll
            for (int o = 16; o > 0; o >>= 1) ps += __shfl_xor_sync(0xffffffffu, ps, o);
            l = l * alpha + ps;
            acc0 *= alpha; acc1 *= alpha; acc2 *= alpha; acc3 *= alpha;
#pragma unroll
            for (int j = 0; j < 32; j++) {
                float pj = __shfl_sync(0xffffffffu, p, j);
                float4 v4 = *(const float4*)&Vs[j * 128 + lane * 4];
                acc0 = fmaf(pj, v4.x, acc0);
                acc1 = fmaf(pj, v4.y, acc1);
                acc2 = fmaf(pj, v4.z, acc2);
                acc3 = fmaf(pj, v4.w, acc3);
            }
            m = m_new;
        }
    }

    float inv = 1.f / l;
    float* optr = O + (size_t)(b * SEQ_ + qrow) * DIM_ + h * HD_ + lane * 4;
    optr[0] = acc0 * inv;
    optr[1] = acc1 * inv;
    optr[2] = acc2 * inv;
    optr[3] = acc3 * inv;
}

// ---------------- launch ----------------
extern "C" void kernel_launch(void* const* d_in, const int* in_sizes, int n_in,
                              void* d_out, int out_size) {
    const float* x = (const float*)d_in[0];
    const float* fcos = (const float*)d_in[1];
    const float* fsin = (const float*)d_in[2];
    const float* Wq = (const float*)d_in[3];
    const float* Wk = (const float*)d_in[4];
    const float* Wv = (const float*)d_in[5];
    const float* Wo = (const float*)d_in[6];
    float* out = (float*)d_out;

    float *qp, *kp, *vp, *ap;
    cudaGetSymbolAddress((void**)&qp, g_q);
    cudaGetSymbolAddress((void**)&kp, g_k);
    cudaGetSymbolAddress((void**)&vp, g_v);
    cudaGetSymbolAddress((void**)&ap, g_attn);

    // QKV projections
    {
        dim3 grid(DIM_ / 128, M_ / 128);
        sgemm_kernel<<<grid, 256>>>(x, Wq, qp, M_, DIM_, DIM_);
    }
    {
        dim3 grid((NKV_ * HD_) / 128, M_ / 128);
        sgemm_kernel<<<grid, 256>>>(x, Wk, kp, M_, NKV_ * HD_, DIM_);
        sgemm_kernel<<<grid, 256>>>(x, Wv, vp, M_, NKV_ * HD_, DIM_);
    }

    // RoPE on Q and K
    {
        int totq = BATCH_ * SEQ_ * NHEADS_ * 64;
        rope_kernel<<<(totq + 255) / 256, 256>>>(qp, fcos, fsin, NHEADS_);
        int totk = BATCH_ * SEQ_ * NKV_ * 64;
        rope_kernel<<<(totk + 255) / 256, 256>>>(kp, fcos, fsin, NKV_);
    }

    // Attention
    {
        dim3 grid(SEQ_ / 8, NHEADS_, BATCH_);
        attn_kernel<<<grid, 256>>>(qp, kp, vp, ap);
    }

    // Output projection
    {
        dim3 grid(DIM_ / 128, M_ / 128);
        sgemm_kernel<<<grid, 256>>>(ap, Wo, out, M_, DIM_, DIM_);
    }
}

// round 2
// speedup vs baseline: 1.3164x; 1.3164x over previous
#include <cuda_runtime.h>
#include <cuda_bf16.h>
#include <math.h>

#define DIM_ 2048
#define SEQ_ 2048
#define BATCH_ 2
#define NHEADS_ 16
#define NKV_ 4
#define HD_ 128
#define M_ (BATCH_ * SEQ_)   // 4096

// ---------------- scratch (no allocations allowed) ----------------
__device__ float g_q[(size_t)M_ * DIM_];          // 4096 x 2048
__device__ float g_k[(size_t)M_ * (NKV_ * HD_)];  // 4096 x 512
__device__ float g_v[(size_t)M_ * (NKV_ * HD_)];  // 4096 x 512
__device__ float g_attn[(size_t)M_ * DIM_];       // 4096 x 2048

__device__ __forceinline__ unsigned f2tf32(float f) {
    unsigned u;
    asm("cvt.rna.tf32.f32 %0, %1;" : "=r"(u) : "f"(f));
    return u;
}

// ---------------- TF32 tensor-core GEMM: C[M,N] = A[M,K] @ B[K,N] ----------------
// BM=128, BN=128, BK=16. 256 threads = 8 warps (2x4), warp tile 64x32.
// Per warp: 4 (m) x 4 (n) m16n8k8 fragments, 2 k-steps per BK.
__global__ __launch_bounds__(256) void gemm_tf32(const float* __restrict__ A,
                                                 const float* __restrict__ B,
                                                 float* __restrict__ C,
                                                 int M, int N, int K) {
    __shared__ float As[128][20];   // [m][k], pad 20 -> conflict-free fragment loads
    __shared__ float Bs[16][136];   // [k][n], pad 136 -> conflict-free fragment loads

    const int tid = threadIdx.x;
    const int bm = blockIdx.y * 128;
    const int bn = blockIdx.x * 128;

    const int w = tid >> 5;
    const int lane = tid & 31;
    const int wm = (w >> 2) * 64;   // warp m offset (0 or 64)
    const int wn = (w & 3) * 32;    // warp n offset
    const int tr = lane >> 2;       // groupID 0..7
    const int tq = lane & 3;        // thread-in-group 0..3

    // A tile load mapping: 128 rows x 16 cols, 8 floats/thread (2 float4)
    const int a_row = tid >> 1;
    const int a_col = (tid & 1) * 8;
    // B tile load mapping: 16 rows x 128 cols, 8 floats/thread (2 float4)
    const int b_row = tid >> 4;
    const int b_col = (tid & 15) * 8;

    float acc[4][4][4];
#pragma unroll
    for (int i = 0; i < 4; i++)
#pragma unroll
        for (int j = 0; j < 4; j++)
#pragma unroll
            for (int r = 0; r < 4; r++) acc[i][j][r] = 0.f;

    for (int k0 = 0; k0 < K; k0 += 16) {
        // load A tile, convert to tf32 bits, store [m][k]
        {
            const float4 v0 = *(const float4*)(A + (size_t)(bm + a_row) * K + k0 + a_col);
            const float4 v1 = *(const float4*)(A + (size_t)(bm + a_row) * K + k0 + a_col + 4);
            float4 t0, t1;
            t0.x = __uint_as_float(f2tf32(v0.x)); t0.y = __uint_as_float(f2tf32(v0.y));
            t0.z = __uint_as_float(f2tf32(v0.z)); t0.w = __uint_as_float(f2tf32(v0.w));
            t1.x = __uint_as_float(f2tf32(v1.x)); t1.y = __uint_as_float(f2tf32(v1.y));
            t1.z = __uint_as_float(f2tf32(v1.z)); t1.w = __uint_as_float(f2tf32(v1.w));
            *(float4*)&As[a_row][a_col] = t0;
            *(float4*)&As[a_row][a_col + 4] = t1;
        }
        // load B tile, convert, store [k][n]
        {
            const float4 v0 = *(const float4*)(B + (size_t)(k0 + b_row) * N + bn + b_col);
            const float4 v1 = *(const float4*)(B + (size_t)(k0 + b_row) * N + bn + b_col + 4);
            float4 t0, t1;
            t0.x = __uint_as_float(f2tf32(v0.x)); t0.y = __uint_as_float(f2tf32(v0.y));
            t0.z = __uint_as_float(f2tf32(v0.z)); t0.w = __uint_as_float(f2tf32(v0.w));
            t1.x = __uint_as_float(f2tf32(v1.x)); t1.y = __uint_as_float(f2tf32(v1.y));
            t1.z = __uint_as_float(f2tf32(v1.z)); t1.w = __uint_as_float(f2tf32(v1.w));
            *(float4*)&Bs[b_row][b_col] = t0;
            *(float4*)&Bs[b_row][b_col + 4] = t1;
        }
        __syncthreads();

#pragma unroll
        for (int kk = 0; kk < 16; kk += 8) {
            unsigned a[4][4];
#pragma unroll
            for (int im = 0; im < 4; im++) {
                const int m0 = wm + im * 16 + tr;
                a[im][0] = __float_as_uint(As[m0][kk + tq]);
                a[im][1] = __float_as_uint(As[m0 + 8][kk + tq]);
                a[im][2] = __float_as_uint(As[m0][kk + tq + 4]);
                a[im][3] = __float_as_uint(As[m0 + 8][kk + tq + 4]);
            }
            unsigned bfr[4][2];
#pragma unroll
            for (int in_ = 0; in_ < 4; in_++) {
                const int n0 = wn + in_ * 8 + tr;
                bfr[in_][0] = __float_as_uint(Bs[kk + tq][n0]);
                bfr[in_][1] = __float_as_uint(Bs[kk + tq + 4][n0]);
            }
#pragma unroll
            for (int im = 0; im < 4; im++)
#pragma unroll
                for (int in_ = 0; in_ < 4; in_++) {
                    asm volatile(
                        "mma.sync.aligned.m16n8k8.row.col.f32.tf32.tf32.f32 "
                        "{%0,%1,%2,%3}, {%4,%5,%6,%7}, {%8,%9}, {%0,%1,%2,%3};"
                        : "+f"(acc[im][in_][0]), "+f"(acc[im][in_][1]),
                          "+f"(acc[im][in_][2]), "+f"(acc[im][in_][3])
                        : "r"(a[im][0]), "r"(a[im][1]), "r"(a[im][2]), "r"(a[im][3]),
                          "r"(bfr[in_][0]), "r"(bfr[in_][1]));
                }
        }
        __syncthreads();
    }

    // epilogue: c0,c1 -> (tr, 2*tq), (tr, 2*tq+1); c2,c3 -> row +8
#pragma unroll
    for (int im = 0; im < 4; im++) {
        const int row0 = bm + wm + im * 16 + tr;
#pragma unroll
        for (int in_ = 0; in_ < 4; in_++) {
            const int col = bn + wn + in_ * 8 + tq * 2;
            *(float2*)(C + (size_t)row0 * N + col) = make_float2(acc[im][in_][0], acc[im][in_][1]);
            *(float2*)(C + (size_t)(row0 + 8) * N + col) = make_float2(acc[im][in_][2], acc[im][in_][3]);
        }
    }
}

// ---------------- RoPE: interleaved pairs, per (b, s, h, i<64) ----------------
__global__ void rope_kernel(float* __restrict__ q, const float* __restrict__ cosf,
                            const float* __restrict__ sinf, int nheads) {
    int idx = blockIdx.x * blockDim.x + threadIdx.x;
    int total = BATCH_ * SEQ_ * nheads * 64;
    if (idx >= total) return;
    int i = idx & 63;
    int h = (idx >> 6) % nheads;
    int s = (idx / (64 * nheads)) % SEQ_;
    int b = idx / (64 * nheads * SEQ_);
    float c = cosf[s * 64 + i];
    float sn = sinf[s * 64 + i];
    float* p = q + ((size_t)(b * SEQ_ + s)) * (nheads * HD_) + h * HD_ + 2 * i;
    float xr = p[0], xi = p[1];
    p[0] = xr * c - xi * sn;
    p[1] = xr * sn + xi * c;
}

// ---------------- Flash-style causal GQA attention ----------------
// Block: 256 threads = 8 warps, 1 warp per q row. Grid: (SEQ/8, NHEADS, BATCH).
__global__ __launch_bounds__(256) void attn_kernel(const float* __restrict__ Q,
                                                   const float* __restrict__ K,
                                                   const float* __restrict__ V,
                                                   float* __restrict__ O) {
    __shared__ float Qs[8][128];
    __shared__ float Ks[128 * 33];   // transposed [d][key], pad 33
    __shared__ float Vs[32 * 128];   // [key][d]

    const int w = threadIdx.x >> 5;
    const int lane = threadIdx.x & 31;
    const int b = blockIdx.z;
    const int h = blockIdx.y;
    const int g = h / (NHEADS_ / NKV_);   // kv head
    const int q0 = blockIdx.x * 8;
    const int qrow = q0 + w;

    const float scale = 0.08838834764831845f;  // 1/sqrt(128)

    const float* qptr = Q + (size_t)(b * SEQ_ + qrow) * DIM_ + h * HD_;
#pragma unroll
    for (int t = lane; t < 128; t += 32) Qs[w][t] = qptr[t] * scale;

    float m = -1e30f, l = 0.f;
    float acc0 = 0.f, acc1 = 0.f, acc2 = 0.f, acc3 = 0.f;

    const float* kbase = K + (size_t)b * SEQ_ * (NKV_ * HD_) + g * HD_;
    const float* vbase = V + (size_t)b * SEQ_ * (NKV_ * HD_) + g * HD_;

    const int nchunk = (q0 + 7) / 32 + 1;
    for (int kb = 0; kb < nchunk; kb++) {
        __syncthreads();
        // stage 32 keys (K transposed, V direct)
        for (int idx = threadIdx.x; idx < 32 * 128; idx += 256) {
            int key = idx >> 7;
            int d = idx & 127;
            size_t goff = (size_t)(kb * 32 + key) * (NKV_ * HD_) + d;
            Ks[d * 33 + key] = kbase[goff];
            Vs[key * 128 + d] = vbase[goff];
        }
        __syncthreads();

        if (kb * 32 <= qrow) {
            const int kglob = kb * 32 + lane;
            float s = 0.f;
#pragma unroll 8
            for (int d = 0; d < 128; d++) s = fmaf(Qs[w][d], Ks[d * 33 + lane], s);
            if (kglob > qrow) s = -1e30f;

            float mx = s;
#pragma unroll
            for (int o = 16; o > 0; o >>= 1) mx = fmaxf(mx, __shfl_xor_sync(0xffffffffu, mx, o));
            float m_new = fmaxf(m, mx);
            float alpha = __expf(m - m_new);
            float p = __expf(s - m_new);
            float ps = p;
#pragma unroll
            for (int o = 16; o > 0; o >>= 1) ps += __shfl_xor_sync(0xffffffffu, ps, o);
            l = l * alpha + ps;
            acc0 *= alpha; acc1 *= alpha; acc2 *= alpha; acc3 *= alpha;
#pragma unroll
            for (int j = 0; j < 32; j++) {
                float pj = __shfl_sync(0xffffffffu, p, j);
                float4 v4 = *(const float4*)&Vs[j * 128 + lane * 4];
                acc0 = fmaf(pj, v4.x, acc0);
                acc1 = fmaf(pj, v4.y, acc1);
                acc2 = fmaf(pj, v4.z, acc2);
                acc3 = fmaf(pj, v4.w, acc3);
            }
            m = m_new;
        }
    }

    float inv = 1.f / l;
    float* optr = O + (size_t)(b * SEQ_ + qrow) * DIM_ + h * HD_ + lane * 4;
    optr[0] = acc0 * inv;
    optr[1] = acc1 * inv;
    optr[2] = acc2 * inv;
    optr[3] = acc3 * inv;
}

// ---------------- launch ----------------
extern "C" void kernel_launch(void* const* d_in, const int* in_sizes, int n_in,
                              void* d_out, int out_size) {
    const float* x = (const float*)d_in[0];
    const float* fcos = (const float*)d_in[1];
    const float* fsin = (const float*)d_in[2];
    const float* Wq = (const float*)d_in[3];
    const float* Wk = (const float*)d_in[4];
    const float* Wv = (const float*)d_in[5];
    const float* Wo = (const float*)d_in[6];
    float* out = (float*)d_out;

    float *qp, *kp, *vp, *ap;
    cudaGetSymbolAddress((void**)&qp, g_q);
    cudaGetSymbolAddress((void**)&kp, g_k);
    cudaGetSymbolAddress((void**)&vp, g_v);
    cudaGetSymbolAddress((void**)&ap, g_attn);

    // QKV projections (tf32 tensor cores)
    {
        dim3 grid(DIM_ / 128, M_ / 128);
        gemm_tf32<<<grid, 256>>>(x, Wq, qp, M_, DIM_, DIM_);
    }
    {
        dim3 grid((NKV_ * HD_) / 128, M_ / 128);
        gemm_tf32<<<grid, 256>>>(x, Wk, kp, M_, NKV_ * HD_, DIM_);
        gemm_tf32<<<grid, 256>>>(x, Wv, vp, M_, NKV_ * HD_, DIM_);
    }

    // RoPE on Q and K
    {
        int totq = BATCH_ * SEQ_ * NHEADS_ * 64;
        rope_kernel<<<(totq + 255) / 256, 256>>>(qp, fcos, fsin, NHEADS_);
        int totk = BATCH_ * SEQ_ * NKV_ * 64;
        rope_kernel<<<(totk + 255) / 256, 256>>>(kp, fcos, fsin, NKV_);
    }

    // Attention
    {
        dim3 grid(SEQ_ / 8, NHEADS_, BATCH_);
        attn_kernel<<<grid, 256>>>(qp, kp, vp, ap);
    }

    // Output projection (tf32 tensor cores)
    {
        dim3 grid(DIM_ / 128, M_ / 128);
        gemm_tf32<<<grid, 256>>>(ap, Wo, out, M_, DIM_, DIM_);
    }
}

// round 4
// speedup vs baseline: 5.0346x; 3.8245x over previous
#include <cuda_runtime.h>
#include <math.h>

#define DIM_ 2048
#define SEQ_ 2048
#define BATCH_ 2
#define NHEADS_ 16
#define NKV_ 4
#define HD_ 128
#define M_ (BATCH_ * SEQ_)   // 4096

// ---------------- scratch ----------------
__device__ float g_q[(size_t)M_ * DIM_];
__device__ float g_k[(size_t)M_ * (NKV_ * HD_)];
__device__ float g_v[(size_t)M_ * (NKV_ * HD_)];
__device__ float g_attn[(size_t)M_ * DIM_];

__device__ __forceinline__ unsigned f2tf32(float f) {
    unsigned u;
    asm("cvt.rna.tf32.f32 %0, %1;" : "=r"(u) : "f"(f));
    return u;
}
__device__ __forceinline__ float cvt32(float f) { return __uint_as_float(f2tf32(f)); }

__device__ __forceinline__ void mma_tf32(float* c, unsigned a0, unsigned a1, unsigned a2,
                                         unsigned a3, unsigned b0, unsigned b1) {
    asm volatile(
        "mma.sync.aligned.m16n8k8.row.col.f32.tf32.tf32.f32 "
        "{%0,%1,%2,%3}, {%4,%5,%6,%7}, {%8,%9}, {%0,%1,%2,%3};"
        : "+f"(c[0]), "+f"(c[1]), "+f"(c[2]), "+f"(c[3])
        : "r"(a0), "r"(a1), "r"(a2), "r"(a3), "r"(b0), "r"(b1));
}

// ---------------- TF32 GEMM, double-buffered, optional fused RoPE ----------------
// BM=BN=128, BK=16, 256 threads = 8 warps (2x4), warp tile 64x32, 4x4 m16n8k8 frags.
template <bool ROPE>
__global__ __launch_bounds__(256) void gemm_tf32(const float* __restrict__ A,
                                                 const float* __restrict__ B,
                                                 float* __restrict__ C,
                                                 int M, int N, int K,
                                                 const float* __restrict__ fcos,
                                                 const float* __restrict__ fsin) {
    __shared__ float As[2][128][20];
    __shared__ float Bs[2][16][136];

    const int tid = threadIdx.x;
    const int bm = blockIdx.y * 128;
    const int bn = blockIdx.x * 128;
    const int w = tid >> 5, lane = tid & 31;
    const int wm = (w >> 2) * 64, wn = (w & 3) * 32;
    const int tr = lane >> 2, tq = lane & 3;
    const int a_row = tid >> 1, a_col = (tid & 1) * 8;
    const int b_row = tid >> 4, b_col = (tid & 15) * 8;

    const float* Aptr = A + (size_t)(bm + a_row) * K + a_col;
    const float* Bptr = B + (size_t)b_row * N + bn + b_col;

    float4 ra0, ra1, rb0, rb1;
    ra0 = *(const float4*)(Aptr);
    ra1 = *(const float4*)(Aptr + 4);
    rb0 = *(const float4*)(Bptr);
    rb1 = *(const float4*)(Bptr + 4);

    // store tile 0 (converted)
    {
        float4 t;
        t.x = cvt32(ra0.x); t.y = cvt32(ra0.y); t.z = cvt32(ra0.z); t.w = cvt32(ra0.w);
        *(float4*)&As[0][a_row][a_col] = t;
        t.x = cvt32(ra1.x); t.y = cvt32(ra1.y); t.z = cvt32(ra1.z); t.w = cvt32(ra1.w);
        *(float4*)&As[0][a_row][a_col + 4] = t;
        t.x = cvt32(rb0.x); t.y = cvt32(rb0.y); t.z = cvt32(rb0.z); t.w = cvt32(rb0.w);
        *(float4*)&Bs[0][b_row][b_col] = t;
        t.x = cvt32(rb1.x); t.y = cvt32(rb1.y); t.z = cvt32(rb1.z); t.w = cvt32(rb1.w);
        *(float4*)&Bs[0][b_row][b_col + 4] = t;
    }
    __syncthreads();

    float acc[4][4][4];
#pragma unroll
    for (int i = 0; i < 4; i++)
#pragma unroll
        for (int j = 0; j < 4; j++)
#pragma unroll
            for (int r = 0; r < 4; r++) acc[i][j][r] = 0.f;

    int cur = 0;
    for (int k0 = 0; k0 < K; k0 += 16) {
        const bool pf = (k0 + 16) < K;
        if (pf) {
            ra0 = *(const float4*)(Aptr + k0 + 16);
            ra1 = *(const float4*)(Aptr + k0 + 20);
            rb0 = *(const float4*)(Bptr + (size_t)(k0 + 16) * N);
            rb1 = *(const float4*)(Bptr + (size_t)(k0 + 16) * N + 4);
        }

#pragma unroll
        for (int kk = 0; kk < 16; kk += 8) {
            unsigned a[4][4];
#pragma unroll
            for (int im = 0; im < 4; im++) {
                const int m0 = wm + im * 16 + tr;
                a[im][0] = __float_as_uint(As[cur][m0][kk + tq]);
                a[im][1] = __float_as_uint(As[cur][m0 + 8][kk + tq]);
                a[im][2] = __float_as_uint(As[cur][m0][kk + tq + 4]);
                a[im][3] = __float_as_uint(As[cur][m0 + 8][kk + tq + 4]);
            }
            unsigned bf[4][2];
#pragma unroll
            for (int in_ = 0; in_ < 4; in_++) {
                const int n0 = wn + in_ * 8 + tr;
                bf[in_][0] = __float_as_uint(Bs[cur][kk + tq][n0]);
                bf[in_][1] = __float_as_uint(Bs[cur][kk + tq + 4][n0]);
            }
#pragma unroll
            for (int im = 0; im < 4; im++)
#pragma unroll
                for (int in_ = 0; in_ < 4; in_++)
                    mma_tf32(acc[im][in_], a[im][0], a[im][1], a[im][2], a[im][3],
                             bf[in_][0], bf[in_][1]);
        }

        if (pf) {
            const int nxt = cur ^ 1;
            float4 t;
            t.x = cvt32(ra0.x); t.y = cvt32(ra0.y); t.z = cvt32(ra0.z); t.w = cvt32(ra0.w);
            *(float4*)&As[nxt][a_row][a_col] = t;
            t.x = cvt32(ra1.x); t.y = cvt32(ra1.y); t.z = cvt32(ra1.z); t.w = cvt32(ra1.w);
            *(float4*)&As[nxt][a_row][a_col + 4] = t;
            t.x = cvt32(rb0.x); t.y = cvt32(rb0.y); t.z = cvt32(rb0.z); t.w = cvt32(rb0.w);
            *(float4*)&Bs[nxt][b_row][b_col] = t;
            t.x = cvt32(rb1.x); t.y = cvt32(rb1.y); t.z = cvt32(rb1.z); t.w = cvt32(rb1.w);
            *(float4*)&Bs[nxt][b_row][b_col + 4] = t;
        }
        __syncthreads();
        cur ^= 1;
    }

#pragma unroll
    for (int im = 0; im < 4; im++) {
        const int row0 = bm + wm + im * 16 + tr;
#pragma unroll
        for (int in_ = 0; in_ < 4; in_++) {
            const int col = bn + wn + in_ * 8 + tq * 2;
            float c0 = acc[im][in_][0], c1 = acc[im][in_][1];
            float c2 = acc[im][in_][2], c3 = acc[im][in_][3];
            if (ROPE) {
                const int i = (col & (HD_ - 1)) >> 1;
                const int s0 = row0 & (SEQ_ - 1);
                const int s1 = (row0 + 8) & (SEQ_ - 1);
                const float cA = fcos[s0 * 64 + i], sA = fsin[s0 * 64 + i];
                const float cB = fcos[s1 * 64 + i], sB = fsin[s1 * 64 + i];
                float r0 = c0 * cA - c1 * sA, i0 = c0 * sA + c1 * cA;
                float r1 = c2 * cB - c3 * sB, i1 = c2 * sB + c3 * cB;
                c0 = r0; c1 = i0; c2 = r1; c3 = i1;
            }
            *(float2*)(C + (size_t)row0 * N + col) = make_float2(c0, c1);
            *(float2*)(C + (size_t)(row0 + 8) * N + col) = make_float2(c2, c3);
        }
    }
}

// ---------------- TF32 mma flash attention ----------------
// Q tile 128 rows/block, K chunk 64. 256 threads = 8 warps; warp owns 16 q-rows, full width.
#define QT 128
#define KT 64
#define QS_STRIDE 132
#define KS_STRIDE 132
#define VS_STRIDE 136
#define PS_STRIDE 68
#define ATTN_SMEM_BYTES ((QT * QS_STRIDE + KT * KS_STRIDE + KT * VS_STRIDE + QT * PS_STRIDE) * 4)

__global__ __launch_bounds__(256) void attn_mma(const float* __restrict__ Q,
                                                const float* __restrict__ K,
                                                const float* __restrict__ V,
                                                float* __restrict__ O) {
    extern __shared__ float sm[];
    float* Qs = sm;                         // [128][132]
    float* Ks = Qs + QT * QS_STRIDE;        // [64][132]
    float* Vs = Ks + KT * KS_STRIDE;        // [64][136]
    float* Ps = Vs + KT * VS_STRIDE;        // [128][68]

    const int tid = threadIdx.x;
    const int w = tid >> 5, lane = tid & 31;
    const int tr = lane >> 2, tq = lane & 3;
    const int b = blockIdx.z, h = blockIdx.y;
    const int g = h / (NHEADS_ / NKV_);
    const int qb = (int)gridDim.x - 1 - (int)blockIdx.x;  // heavy blocks first
    const int q0 = qb * QT;
    const int wm = w * 16;
    const float scale = 0.08838834764831845f;

    // stage Q (scaled + tf32)
    {
        const float* qbase = Q + (size_t)(b * SEQ_ + q0) * DIM_ + h * HD_;
        for (int i = tid; i < QT * 32; i += 256) {
            int r = i >> 5, c4 = (i & 31) * 4;
            float4 v = *(const float4*)(qbase + (size_t)r * DIM_ + c4);
            Qs[r * QS_STRIDE + c4 + 0] = cvt32(v.x * scale);
            Qs[r * QS_STRIDE + c4 + 1] = cvt32(v.y * scale);
            Qs[r * QS_STRIDE + c4 + 2] = cvt32(v.z * scale);
            Qs[r * QS_STRIDE + c4 + 3] = cvt32(v.w * scale);
        }
    }

    float m0 = -1e30f, m1 = -1e30f, l0 = 0.f, l1 = 0.f;
    float o[16][4];
#pragma unroll
    for (int j = 0; j < 16; j++)
#pragma unroll
        for (int r = 0; r < 4; r++) o[j][r] = 0.f;

    const float* kbase = K + (size_t)b * SEQ_ * (NKV_ * HD_) + g * HD_;
    const float* vbase = V + (size_t)b * SEQ_ * (NKV_ * HD_) + g * HD_;

    const int nchunk = q0 / KT + 2;
    for (int kb = 0; kb < nchunk; kb++) {
        const int key0 = kb * KT;
        __syncthreads();
        for (int i = tid; i < KT * 32; i += 256) {
            int r = i >> 5, c4 = (i & 31) * 4;
            size_t go = (size_t)(key0 + r) * (NKV_ * HD_) + c4;
            float4 kv = *(const float4*)(kbase + go);
            float4 vv = *(const float4*)(vbase + go);
            Ks[r * KS_STRIDE + c4 + 0] = cvt32(kv.x);
            Ks[r * KS_STRIDE + c4 + 1] = cvt32(kv.y);
            Ks[r * KS_STRIDE + c4 + 2] = cvt32(kv.z);
            Ks[r * KS_STRIDE + c4 + 3] = cvt32(kv.w);
            Vs[r * VS_STRIDE + c4 + 0] = cvt32(vv.x);
            Vs[r * VS_STRIDE + c4 + 1] = cvt32(vv.y);
            Vs[r * VS_STRIDE + c4 + 2] = cvt32(vv.z);
            Vs[r * VS_STRIDE + c4 + 3] = cvt32(vv.w);
        }
        __syncthreads();

        // S = Q K^T  (warp: 16 rows x 64 keys)
        float s[8][4];
#pragma unroll
        for (int in_ = 0; in_ < 8; in_++)
#pragma unroll
            for (int r = 0; r < 4; r++) s[in_][r] = 0.f;

#pragma unroll
        for (int kk = 0; kk < HD_; kk += 8) {
            unsigned a0 = __float_as_uint(Qs[(wm + tr) * QS_STRIDE + kk + tq]);
            unsigned a1 = __float_as_uint(Qs[(wm + tr + 8) * QS_STRIDE + kk + tq]);
            unsigned a2 = __float_as_uint(Qs[(wm + tr) * QS_STRIDE + kk + tq + 4]);
            unsigned a3 = __float_as_uint(Qs[(wm + tr + 8) * QS_STRIDE + kk + tq + 4]);
#pragma unroll
            for (int in_ = 0; in_ < 8; in_++) {
                unsigned b0 = __float_as_uint(Ks[(in_ * 8 + tr) * KS_STRIDE + kk + tq]);
                unsigned b1 = __float_as_uint(Ks[(in_ * 8 + tr) * KS_STRIDE + kk + tq + 4]);
                mma_tf32(s[in_], a0, a1, a2, a3, b0, b1);
            }
        }

        // causal mask (only chunks that can cross the diagonal)
        if (key0 + KT - 1 > q0) {
            const int r0 = q0 + wm + tr, r1 = r0 + 8;
#pragma unroll
            for (int in_ = 0; in_ < 8; in_++) {
                const int c = key0 + in_ * 8 + 2 * tq;
                if (c > r0) s[in_][0] = -1e30f;
                if (c + 1 > r0) s[in_][1] = -1e30f;
                if (c > r1) s[in_][2] = -1e30f;
                if (c + 1 > r1) s[in_][3] = -1e30f;
            }
        }

        // online softmax (row groups: tr -> m0/l0, tr+8 -> m1/l1)
        float mx0 = -1e30f, mx1 = -1e30f;
#pragma unroll
        for (int in_ = 0; in_ < 8; in_++) {
            mx0 = fmaxf(mx0, fmaxf(s[in_][0], s[in_][1]));
            mx1 = fmaxf(mx1, fmaxf(s[in_][2], s[in_][3]));
        }
        mx0 = fmaxf(mx0, __shfl_xor_sync(0xffffffffu, mx0, 1));
        mx0 = fmaxf(mx0, __shfl_xor_sync(0xffffffffu, mx0, 2));
        mx1 = fmaxf(mx1, __shfl_xor_sync(0xffffffffu, mx1, 1));
        mx1 = fmaxf(mx1, __shfl_xor_sync(0xffffffffu, mx1, 2));

        const float nm0 = fmaxf(m0, mx0), nm1 = fmaxf(m1, mx1);
        const float al0 = __expf(m0 - nm0), al1 = __expf(m1 - nm1);
        float sum0 = 0.f, sum1 = 0.f;
#pragma unroll
        for (int in_ = 0; in_ < 8; in_++) {
            s[in_][0] = __expf(s[in_][0] - nm0);
            s[in_][1] = __expf(s[in_][1] - nm0);
            s[in_][2] = __expf(s[in_][2] - nm1);
            s[in_][3] = __expf(s[in_][3] - nm1);
            sum0 += s[in_][0] + s[in_][1];
            sum1 += s[in_][2] + s[in_][3];
        }
        sum0 += __shfl_xor_sync(0xffffffffu, sum0, 1);
        sum0 += __shfl_xor_sync(0xffffffffu, sum0, 2);
        sum1 += __shfl_xor_sync(0xffffffffu, sum1, 1);
        sum1 += __shfl_xor_sync(0xffffffffu, sum1, 2);
        l0 = l0 * al0 + sum0;
        l1 = l1 * al1 + sum1;
        m0 = nm0; m1 = nm1;

#pragma unroll
        for (int j = 0; j < 16; j++) {
            o[j][0] *= al0; o[j][1] *= al0;
            o[j][2] *= al1; o[j][3] *= al1;
        }

        // P -> smem (warp-local rows), tf32
#pragma unroll
        for (int in_ = 0; in_ < 8; in_++) {
            const int c = in_ * 8 + 2 * tq;
            Ps[(wm + tr) * PS_STRIDE + c] = cvt32(s[in_][0]);
            Ps[(wm + tr) * PS_STRIDE + c + 1] = cvt32(s[in_][1]);
            Ps[(wm + tr + 8) * PS_STRIDE + c] = cvt32(s[in_][2]);
            Ps[(wm + tr + 8) * PS_STRIDE + c + 1] = cvt32(s[in_][3]);
        }
        __syncwarp();

        // O += P V  (warp: 16 rows x 128 dims)
#pragma unroll
        for (int kk = 0; kk < KT; kk += 8) {
            unsigned a0 = __float_as_uint(Ps[(wm + tr) * PS_STRIDE + kk + tq]);
            unsigned a1 = __float_as_uint(Ps[(wm + tr + 8) * PS_STRIDE + kk + tq]);
            unsigned a2 = __float_as_uint(Ps[(wm + tr) * PS_STRIDE + kk + tq + 4]);
            unsigned a3 = __float_as_uint(Ps[(wm + tr + 8) * PS_STRIDE + kk + tq + 4]);
#pragma unroll
            for (int j = 0; j < 16; j++) {
                unsigned b0 = __float_as_uint(Vs[(kk + tq) * VS_STRIDE + j * 8 + tr]);
                unsigned b1 = __float_as_uint(Vs[(kk + tq + 4) * VS_STRIDE + j * 8 + tr]);
                mma_tf32(o[j], a0, a1, a2, a3, b0, b1);
            }
        }
    }

    const float inv0 = 1.f / l0, inv1 = 1.f / l1;
    float* obase = O + (size_t)(b * SEQ_ + q0) * DIM_ + h * HD_;
#pragma unroll
    for (int j = 0; j < 16; j++) {
        const int c = j * 8 + 2 * tq;
        *(float2*)(obase + (size_t)(wm + tr) * DIM_ + c) =
            make_float2(o[j][0] * inv0, o[j][1] * inv0);
        *(float2*)(obase + (size_t)(wm + tr + 8) * DIM_ + c) =
            make_float2(o[j][2] * inv1, o[j][3] * inv1);
    }
}

// ---------------- launch ----------------
extern "C" void kernel_launch(void* const* d_in, const int* in_sizes, int n_in,
                              void* d_out, int out_size) {
    const float* x = (const float*)d_in[0];
    const float* fcos = (const float*)d_in[1];
    const float* fsin = (const float*)d_in[2];
    const float* Wq = (const float*)d_in[3];
    const float* Wk = (const float*)d_in[4];
    const float* Wv = (const float*)d_in[5];
    const float* Wo = (const float*)d_in[6];
    float* out = (float*)d_out;

    float *qp, *kp, *vp, *ap;
    cudaGetSymbolAddress((void**)&qp, g_q);
    cudaGetSymbolAddress((void**)&kp, g_k);
    cudaGetSymbolAddress((void**)&vp, g_v);
    cudaGetSymbolAddress((void**)&ap, g_attn);

    cudaFuncSetAttribute(attn_mma, cudaFuncAttributeMaxDynamicSharedMemorySize,
                         ATTN_SMEM_BYTES);

    // Q projection + fused RoPE
    {
        dim3 grid(DIM_ / 128, M_ / 128);
        gemm_tf32<true><<<grid, 256>>>(x, Wq, qp, M_, DIM_, DIM_, fcos, fsin);
    }
    // K projection + fused RoPE, V projection
    {
        dim3 grid((NKV_ * HD_) / 128, M_ / 128);
        gemm_tf32<true><<<grid, 256>>>(x, Wk, kp, M_, NKV_ * HD_, DIM_, fcos, fsin);
        gemm_tf32<false><<<grid, 256>>>(x, Wv, vp, M_, NKV_ * HD_, DIM_, nullptr, nullptr);
    }
    // Attention (tf32 mma flash)
    {
        dim3 grid(SEQ_ / QT, NHEADS_, BATCH_);
        attn_mma<<<grid, 256, ATTN_SMEM_BYTES>>>(qp, kp, vp, ap);
    }
    // Output projection
    {
        dim3 grid(DIM_ / 128, M_ / 128);
        gemm_tf32<false><<<grid, 256>>>(ap, Wo, out, M_, DIM_, DIM_, nullptr, nullptr);
    }
}

// round 10
// speedup vs baseline: 5.1659x; 1.0261x over previous
#include <cuda_runtime.h>
#include <math.h>
#include <stdint.h>

#define DIM_ 2048
#define SEQ_ 2048
#define BATCH_ 2
#define NHEADS_ 16
#define NKV_ 4
#define HD_ 128
#define M_ (BATCH_ * SEQ_)   // 4096

// ---------------- scratch ----------------
__device__ float g_q[(size_t)M_ * DIM_];
__device__ float g_k[(size_t)M_ * (NKV_ * HD_)];
__device__ float g_v[(size_t)M_ * (NKV_ * HD_)];
__device__ float g_attn[(size_t)M_ * DIM_];
__device__ float g_x32[(size_t)M_ * DIM_];              // x, tf32-rounded
__device__ float g_wqT[(size_t)DIM_ * DIM_];            // Wq^T [N][K], tf32-rounded
__device__ float g_wkT[(size_t)(NKV_ * HD_) * DIM_];
__device__ float g_wvT[(size_t)(NKV_ * HD_) * DIM_];
__device__ float g_woT[(size_t)DIM_ * DIM_];

__device__ __forceinline__ unsigned f2tf32(float f) {
    unsigned u;
    asm("cvt.rna.tf32.f32 %0, %1;" : "=r"(u) : "f"(f));
    return u;
}
__device__ __forceinline__ float cvt32(float f) { return __uint_as_float(f2tf32(f)); }

__device__ __forceinline__ uint32_t smem_u32(const void* p) {
    uint32_t a;
    asm("{ .reg .u64 t; cvta.to.shared.u64 t, %1; cvt.u32.u64 %0, t; }" : "=r"(a) : "l"(p));
    return a;
}
__device__ __forceinline__ void cp_async16(uint32_t saddr, const void* g) {
    asm volatile("cp.async.cg.shared.global [%0], [%1], 16;" :: "r"(saddr), "l"(g));
}
#define CP_COMMIT() asm volatile("cp.async.commit_group;")
#define CP_WAIT1()  asm volatile("cp.async.wait_group 1;")
#define CP_WAIT0()  asm volatile("cp.async.wait_group 0;")

__device__ __forceinline__ void mma_tf32(float* c, unsigned a0, unsigned a1, unsigned a2,
                                         unsigned a3, unsigned b0, unsigned b1) {
    asm volatile(
        "mma.sync.aligned.m16n8k8.row.col.f32.tf32.tf32.f32 "
        "{%0,%1,%2,%3}, {%4,%5,%6,%7}, {%8,%9}, {%0,%1,%2,%3};"
        : "+f"(c[0]), "+f"(c[1]), "+f"(c[2]), "+f"(c[3])
        : "r"(a0), "r"(a1), "r"(a2), "r"(a3), "r"(b0), "r"(b1));
}

// ---------------- prepass: elementwise tf32 round ----------------
__global__ void cvt_tf32_kernel(const float* __restrict__ in, float* __restrict__ out, int n4) {
    int i = blockIdx.x * blockDim.x + threadIdx.x;
    if (i >= n4) return;
    float4 v = ((const float4*)in)[i];
    v.x = cvt32(v.x); v.y = cvt32(v.y); v.z = cvt32(v.z); v.w = cvt32(v.w);
    ((float4*)out)[i] = v;
}

// ---------------- prepass: transpose + tf32 round (in [R][C] -> out [C][R]) ----------------
__global__ void transpose_cvt_kernel(const float* __restrict__ in, float* __restrict__ out,
                                     int R, int C) {
    __shared__ float t[32][33];
    const int bx = blockIdx.x * 32, by = blockIdx.y * 32;
    const int tx = threadIdx.x, ty = threadIdx.y;
#pragma unroll
    for (int j = 0; j < 32; j += 8)
        t[ty + j][tx] = cvt32(in[(size_t)(by + ty + j) * C + bx + tx]);
    __syncthreads();
#pragma unroll
    for (int j = 0; j < 32; j += 8)
        out[(size_t)(bx + ty + j) * R + by + tx] = t[tx][ty + j];
}

// ---------------- cp.async 3-stage TF32 GEMM: C[M,N] = A[M,K] @ BT[N,K]^T ----------------
// Inputs pre-rounded to tf32. BM=BN=128, BK=16, 256 threads = 8 warps (2x4), warp 64x32.
#define GSTRD 20
#define GTILE (128 * GSTRD)             // floats per matrix per stage
#define GSTAGE_FLOATS (2 * GTILE)       // A + B
#define GEMM_SMEM (3 * GSTAGE_FLOATS * 4)

template <bool RND>
__global__ __launch_bounds__(256) void gemm_async(const float* __restrict__ A,
                                                  const float* __restrict__ BT,
                                                  float* __restrict__ C,
                                                  int Mdim, int Ndim, int Kdim) {
    extern __shared__ float smf[];
    const uint32_t smbase = smem_u32(smf);

    const int tid = threadIdx.x;
    const int bm = blockIdx.y * 128;
    const int bn = blockIdx.x * 128;
    const int w = tid >> 5, lane = tid & 31;
    const int wm = (w >> 2) * 64, wn = (w & 3) * 32;
    const int tr = lane >> 2, tq = lane & 3;
    const int ld_row = tid >> 1, ld_col = (tid & 1) * 8;

    const float* Ag = A + (size_t)(bm + ld_row) * Kdim + ld_col;
    const float* Bg = BT + (size_t)(bn + ld_row) * Kdim + ld_col;
    const uint32_t sA = smbase + (ld_row * GSTRD + ld_col) * 4;
    const uint32_t sB = sA + GTILE * 4;

    const int nch = Kdim / 16;

    // prologue: stages 0,1
#pragma unroll
    for (int c = 0; c < 2; c++) {
        const uint32_t off = c * GSTAGE_FLOATS * 4;
        cp_async16(sA + off, Ag + c * 16);
        cp_async16(sA + off + 16, Ag + c * 16 + 4);
        cp_async16(sB + off, Bg + c * 16);
        cp_async16(sB + off + 16, Bg + c * 16 + 4);
        CP_COMMIT();
    }

    float acc[4][4][4];
#pragma unroll
    for (int i = 0; i < 4; i++)
#pragma unroll
        for (int j = 0; j < 4; j++)
#pragma unroll
            for (int r = 0; r < 4; r++) acc[i][j][r] = 0.f;

    for (int c = 0; c < nch; c++) {
        CP_WAIT1();
        __syncthreads();

        if (c + 2 < nch) {
            const uint32_t off = ((c + 2) % 3) * GSTAGE_FLOATS * 4;
            cp_async16(sA + off, Ag + (c + 2) * 16);
            cp_async16(sA + off + 16, Ag + (c + 2) * 16 + 4);
            cp_async16(sB + off, Bg + (c + 2) * 16);
            cp_async16(sB + off + 16, Bg + (c + 2) * 16 + 4);
        }
        CP_COMMIT();

        const float* As = smf + (c % 3) * GSTAGE_FLOATS;
        const float* Bs = As + GTILE;

#pragma unroll
        for (int kk = 0; kk < 16; kk += 8) {
            unsigned a[4][4];
#pragma unroll
            for (int im = 0; im < 4; im++) {
                const int m0 = wm + im * 16 + tr;
                a[im][0] = __float_as_uint(As[m0 * GSTRD + kk + tq]);
                a[im][1] = __float_as_uint(As[(m0 + 8) * GSTRD + kk + tq]);
                a[im][2] = __float_as_uint(As[m0 * GSTRD + kk + tq + 4]);
                a[im][3] = __float_as_uint(As[(m0 + 8) * GSTRD + kk + tq + 4]);
            }
            unsigned bf[4][2];
#pragma unroll
            for (int in_ = 0; in_ < 4; in_++) {
                const int n0 = wn + in_ * 8 + tr;
                bf[in_][0] = __float_as_uint(Bs[n0 * GSTRD + kk + tq]);
                bf[in_][1] = __float_as_uint(Bs[n0 * GSTRD + kk + tq + 4]);
            }
#pragma unroll
            for (int im = 0; im < 4; im++)
#pragma unroll
                for (int in_ = 0; in_ < 4; in_++)
                    mma_tf32(acc[im][in_], a[im][0], a[im][1], a[im][2], a[im][3],
                             bf[in_][0], bf[in_][1]);
        }
    }
    CP_WAIT0();

#pragma unroll
    for (int im = 0; im < 4; im++) {
        const int row0 = bm + wm + im * 16 + tr;
#pragma unroll
        for (int in_ = 0; in_ < 4; in_++) {
            const int col = bn + wn + in_ * 8 + tq * 2;
            float c0 = acc[im][in_][0], c1 = acc[im][in_][1];
            float c2 = acc[im][in_][2], c3 = acc[im][in_][3];
            if (RND) { c0 = cvt32(c0); c1 = cvt32(c1); c2 = cvt32(c2); c3 = cvt32(c3); }
            *(float2*)(C + (size_t)row0 * Ndim + col) = make_float2(c0, c1);
            *(float2*)(C + (size_t)(row0 + 8) * Ndim + col) = make_float2(c2, c3);
        }
    }
}

// ---------------- RoPE: rounds output to tf32, optional scale (for Q) ----------------
__global__ void rope_kernel(float* __restrict__ q, const float* __restrict__ cosf,
                            const float* __restrict__ sinf, int nheads, float outscale) {
    int idx = blockIdx.x * blockDim.x + threadIdx.x;
    int total = BATCH_ * SEQ_ * nheads * 64;
    if (idx >= total) return;
    int i = idx & 63;
    int h = (idx >> 6) % nheads;
    int s = (idx / (64 * nheads)) % SEQ_;
    int b = idx / (64 * nheads * SEQ_);
    float c = cosf[s * 64 + i];
    float sn = sinf[s * 64 + i];
    float* p = q + ((size_t)(b * SEQ_ + s)) * (nheads * HD_) + h * HD_ + 2 * i;
    float xr = p[0], xi = p[1];
    p[0] = cvt32((xr * c - xi * sn) * outscale);
    p[1] = cvt32((xr * sn + xi * c) * outscale);
}

// ---------------- TF32 mma flash attention (inputs pre-rounded/pre-scaled) ----------------
#define QT 128
#define KT 64
#define QS_STRIDE 132
#define KS_STRIDE 132
#define VS_STRIDE 136
#define PS_STRIDE 68
#define ATTN_SMEM_BYTES ((QT * QS_STRIDE + KT * KS_STRIDE + KT * VS_STRIDE + QT * PS_STRIDE) * 4)

__global__ __launch_bounds__(256) void attn_mma(const float* __restrict__ Q,
                                                const float* __restrict__ K,
                                                const float* __restrict__ V,
                                                float* __restrict__ O) {
    extern __shared__ float sm[];
    float* Qs = sm;
    float* Ks = Qs + QT * QS_STRIDE;
    float* Vs = Ks + KT * KS_STRIDE;
    float* Ps = Vs + KT * VS_STRIDE;

    const int tid = threadIdx.x;
    const int w = tid >> 5, lane = tid & 31;
    const int tr = lane >> 2, tq = lane & 3;
    const int b = blockIdx.z, h = blockIdx.y;
    const int g = h / (NHEADS_ / NKV_);
    const int qb = (int)gridDim.x - 1 - (int)blockIdx.x;
    const int q0 = qb * QT;
    const int wm = w * 16;

    {
        const float* qbase = Q + (size_t)(b * SEQ_ + q0) * DIM_ + h * HD_;
        for (int i = tid; i < QT * 32; i += 256) {
            int r = i >> 5, c4 = (i & 31) * 4;
            *(float4*)&Qs[r * QS_STRIDE + c4] = *(const float4*)(qbase + (size_t)r * DIM_ + c4);
        }
    }

    float m0 = -1e30f, m1 = -1e30f, l0 = 0.f, l1 = 0.f;
    float o[16][4];
#pragma unroll
    for (int j = 0; j < 16; j++)
#pragma unroll
        for (int r = 0; r < 4; r++) o[j][r] = 0.f;

    const float* kbase = K + (size_t)b * SEQ_ * (NKV_ * HD_) + g * HD_;
    const float* vbase = V + (size_t)b * SEQ_ * (NKV_ * HD_) + g * HD_;

    const int nchunk = q0 / KT + 2;
    for (int kb = 0; kb < nchunk; kb++) {
        const int key0 = kb * KT;
        __syncthreads();
        for (int i = tid; i < KT * 32; i += 256) {
            int r = i >> 5, c4 = (i & 31) * 4;
            size_t go = (size_t)(key0 + r) * (NKV_ * HD_) + c4;
            *(float4*)&Ks[r * KS_STRIDE + c4] = *(const float4*)(kbase + go);
            *(float4*)&Vs[r * VS_STRIDE + c4] = *(const float4*)(vbase + go);
        }
        __syncthreads();

        float s[8][4];
#pragma unroll
        for (int in_ = 0; in_ < 8; in_++)
#pragma unroll
            for (int r = 0; r < 4; r++) s[in_][r] = 0.f;

#pragma unroll
        for (int kk = 0; kk < HD_; kk += 8) {
            unsigned a0 = __float_as_uint(Qs[(wm + tr) * QS_STRIDE + kk + tq]);
            unsigned a1 = __float_as_uint(Qs[(wm + tr + 8) * QS_STRIDE + kk + tq]);
            unsigned a2 = __float_as_uint(Qs[(wm + tr) * QS_STRIDE + kk + tq + 4]);
            unsigned a3 = __float_as_uint(Qs[(wm + tr + 8) * QS_STRIDE + kk + tq + 4]);
#pragma unroll
            for (int in_ = 0; in_ < 8; in_++) {
                unsigned b0 = __float_as_uint(Ks[(in_ * 8 + tr) * KS_STRIDE + kk + tq]);
                unsigned b1 = __float_as_uint(Ks[(in_ * 8 + tr) * KS_STRIDE + kk + tq + 4]);
                mma_tf32(s[in_], a0, a1, a2, a3, b0, b1);
            }
        }

        if (key0 + KT - 1 > q0) {
            const int r0 = q0 + wm + tr, r1 = r0 + 8;
#pragma unroll
            for (int in_ = 0; in_ < 8; in_++) {
                const int c = key0 + in_ * 8 + 2 * tq;
                if (c > r0) s[in_][0] = -1e30f;
                if (c + 1 > r0) s[in_][1] = -1e30f;
                if (c > r1) s[in_][2] = -1e30f;
                if (c + 1 > r1) s[in_][3] = -1e30f;
            }
        }

        float mx0 = -1e30f, mx1 = -1e30f;
#pragma unroll
        for (int in_ = 0; in_ < 8; in_++) {
            mx0 = fmaxf(mx0, fmaxf(s[in_][0], s[in_][1]));
            mx1 = fmaxf(mx1, fmaxf(s[in_][2], s[in_][3]));
        }
        mx0 = fmaxf(mx0, __shfl_xor_sync(0xffffffffu, mx0, 1));
        mx0 = fmaxf(mx0, __shfl_xor_sync(0xffffffffu, mx0, 2));
        mx1 = fmaxf(mx1, __shfl_xor_sync(0xffffffffu, mx1, 1));
        mx1 = fmaxf(mx1, __shfl_xor_sync(0xffffffffu, mx1, 2));

        const float nm0 = fmaxf(m0, mx0), nm1 = fmaxf(m1, mx1);
        const float al0 = __expf(m0 - nm0), al1 = __expf(m1 - nm1);
        float sum0 = 0.f, sum1 = 0.f;
#pragma unroll
        for (int in_ = 0; in_ < 8; in_++) {
            s[in_][0] = __expf(s[in_][0] - nm0);
            s[in_][1] = __expf(s[in_][1] - nm0);
            s[in_][2] = __expf(s[in_][2] - nm1);
            s[in_][3] = __expf(s[in_][3] - nm1);
            sum0 += s[in_][0] + s[in_][1];
            sum1 += s[in_][2] + s[in_][3];
        }
        sum0 += __shfl_xor_sync(0xffffffffu, sum0, 1);
        sum0 += __shfl_xor_sync(0xffffffffu, sum0, 2);
        sum1 += __shfl_xor_sync(0xffffffffu, sum1, 1);
        sum1 += __shfl_xor_sync(0xffffffffu, sum1, 2);
        l0 = l0 * al0 + sum0;
        l1 = l1 * al1 + sum1;
        m0 = nm0; m1 = nm1;

#pragma unroll
        for (int j = 0; j < 16; j++) {
            o[j][0] *= al0; o[j][1] *= al0;
            o[j][2] *= al1; o[j][3] *= al1;
        }

#pragma unroll
        for (int in_ = 0; in_ < 8; in_++) {
            const int c = in_ * 8 + 2 * tq;
            Ps[(wm + tr) * PS_STRIDE + c] = cvt32(s[in_][0]);
            Ps[(wm + tr) * PS_STRIDE + c + 1] = cvt32(s[in_][1]);
            Ps[(wm + tr + 8) * PS_STRIDE + c] = cvt32(s[in_][2]);
            Ps[(wm + tr + 8) * PS_STRIDE + c + 1] = cvt32(s[in_][3]);
        }
        __syncwarp();

#pragma unroll
        for (int kk = 0; kk < KT; kk += 8) {
            unsigned a0 = __float_as_uint(Ps[(wm + tr) * PS_STRIDE + kk + tq]);
            unsigned a1 = __float_as_uint(Ps[(wm + tr + 8) * PS_STRIDE + kk + tq]);
            unsigned a2 = __float_as_uint(Ps[(wm + tr) * PS_STRIDE + kk + tq + 4]);
            unsigned a3 = __float_as_uint(Ps[(wm + tr + 8) * PS_STRIDE + kk + tq + 4]);
#pragma unroll
            for (int j = 0; j < 16; j++) {
                unsigned b0 = __float_as_uint(Vs[(kk + tq) * VS_STRIDE + j * 8 + tr]);
                unsigned b1 = __float_as_uint(Vs[(kk + tq + 4) * VS_STRIDE + j * 8 + tr]);
                mma_tf32(o[j], a0, a1, a2, a3, b0, b1);
            }
        }
    }

    const float inv0 = 1.f / l0, inv1 = 1.f / l1;
    float* obase = O + (size_t)(b * SEQ_ + q0) * DIM_ + h * HD_;
#pragma unroll
    for (int j = 0; j < 16; j++) {
        const int c = j * 8 + 2 * tq;
        *(float2*)(obase + (size_t)(wm + tr) * DIM_ + c) =
            make_float2(cvt32(o[j][0] * inv0), cvt32(o[j][1] * inv0));
        *(float2*)(obase + (size_t)(wm + tr + 8) * DIM_ + c) =
            make_float2(cvt32(o[j][2] * inv1), cvt32(o[j][3] * inv1));
    }
}

// ---------------- launch ----------------
extern "C" void kernel_launch(void* const* d_in, const int* in_sizes, int n_in,
                              void* d_out, int out_size) {
    const float* x = (const float*)d_in[0];
    const float* fcos = (const float*)d_in[1];
    const float* fsin = (const float*)d_in[2];
    const float* Wq = (const float*)d_in[3];
    const float* Wk = (const float*)d_in[4];
    const float* Wv = (const float*)d_in[5];
    const float* Wo = (const float*)d_in[6];
    float* out = (float*)d_out;

    float *qp, *kp, *vp, *ap, *x32, *wqT, *wkT, *wvT, *woT;
    cudaGetSymbolAddress((void**)&qp, g_q);
    cudaGetSymbolAddress((void**)&kp, g_k);
    cudaGetSymbolAddress((void**)&vp, g_v);
    cudaGetSymbolAddress((void**)&ap, g_attn);
    cudaGetSymbolAddress((void**)&x32, g_x32);
    cudaGetSymbolAddress((void**)&wqT, g_wqT);
    cudaGetSymbolAddress((void**)&wkT, g_wkT);
    cudaGetSymbolAddress((void**)&wvT, g_wvT);
    cudaGetSymbolAddress((void**)&woT, g_woT);

    cudaFuncSetAttribute(attn_mma, cudaFuncAttributeMaxDynamicSharedMemorySize, ATTN_SMEM_BYTES);
    cudaFuncSetAttribute(gemm_async<false>, cudaFuncAttributeMaxDynamicSharedMemorySize, GEMM_SMEM);
    cudaFuncSetAttribute(gemm_async<true>, cudaFuncAttributeMaxDynamicSharedMemorySize, GEMM_SMEM);

    // prepass: tf32-round x, transpose+round weights
    {
        int n4 = M_ * DIM_ / 4;
        cvt_tf32_kernel<<<(n4 + 255) / 256, 256>>>(x, x32, n4);
        dim3 blk(32, 8);
        transpose_cvt_kernel<<<dim3(DIM_ / 32, DIM_ / 32), blk>>>(Wq, wqT, DIM_, DIM_);
        transpose_cvt_kernel<<<dim3((NKV_ * HD_) / 32, DIM_ / 32), blk>>>(Wk, wkT, DIM_, NKV_ * HD_);
        transpose_cvt_kernel<<<dim3((NKV_ * HD_) / 32, DIM_ / 32), blk>>>(Wv, wvT, DIM_, NKV_ * HD_);
        transpose_cvt_kernel<<<dim3(DIM_ / 32, DIM_ / 32), blk>>>(Wo, woT, DIM_, DIM_);
    }

    // projections (V rounds its output for attention staging)
    gemm_async<false><<<dim3(DIM_ / 128, M_ / 128), 256, GEMM_SMEM>>>(x32, wqT, qp, M_, DIM_, DIM_);
    gemm_async<false><<<dim3((NKV_ * HD_) / 128, M_ / 128), 256, GEMM_SMEM>>>(x32, wkT, kp, M_, NKV_ * HD_, DIM_);
    gemm_async<true><<<dim3((NKV_ * HD_) / 128, M_ / 128), 256, GEMM_SMEM>>>(x32, wvT, vp, M_, NKV_ * HD_, DIM_);

    // RoPE (rounds; Q also pre-scaled by 1/sqrt(HD))
    {
        int totq = BATCH_ * SEQ_ * NHEADS_ * 64;
        rope_kernel<<<(totq + 255) / 256, 256>>>(qp, fcos, fsin, NHEADS_, 0.08838834764831845f);
        int totk = BATCH_ * SEQ_ * NKV_ * 64;
        rope_kernel<<<(totk + 255) / 256, 256>>>(kp, fcos, fsin, NKV_, 1.0f);
    }

    // attention
    {
        dim3 grid(SEQ_ / QT, NHEADS_, BATCH_);
        attn_mma<<<grid, 256, ATTN_SMEM_BYTES>>>(qp, kp, vp, ap);
    }

    // output projection
    gemm_async<false><<<dim3(DIM_ / 128, M_ / 128), 256, GEMM_SMEM>>>(ap, woT, out, M_, DIM_, DIM_);
}

// round 11
// speedup vs baseline: 6.3328x; 1.2259x over previous
#include <cuda_runtime.h>
#include <math.h>
#include <stdint.h>

#define DIM_ 2048
#define SEQ_ 2048
#define BATCH_ 2
#define NHEADS_ 16
#define NKV_ 4
#define HD_ 128
#define M_ (BATCH_ * SEQ_)   // 4096

// ---------------- scratch ----------------
__device__ float g_q[(size_t)M_ * DIM_];
__device__ float g_k[(size_t)M_ * (NKV_ * HD_)];
__device__ float g_v[(size_t)M_ * (NKV_ * HD_)];
__device__ float g_attn[(size_t)M_ * DIM_];
__device__ float g_x32[(size_t)M_ * DIM_];              // fragment-packed A (x, later attn)
__device__ float g_wqT[(size_t)DIM_ * DIM_];            // fragment-packed B
__device__ float g_wkT[(size_t)(NKV_ * HD_) * DIM_];
__device__ float g_wvT[(size_t)(NKV_ * HD_) * DIM_];
__device__ float g_woT[(size_t)DIM_ * DIM_];

__device__ __forceinline__ unsigned f2tf32(float f) {
    unsigned u;
    asm("cvt.rna.tf32.f32 %0, %1;" : "=r"(u) : "f"(f));
    return u;
}
__device__ __forceinline__ float cvt32(float f) { return __uint_as_float(f2tf32(f)); }

__device__ __forceinline__ uint32_t smem_u32(const void* p) {
    uint32_t a;
    asm("{ .reg .u64 t; cvta.to.shared.u64 t, %1; cvt.u32.u64 %0, t; }" : "=r"(a) : "l"(p));
    return a;
}
__device__ __forceinline__ void cp_async16(uint32_t saddr, const void* g) {
    asm volatile("cp.async.cg.shared.global [%0], [%1], 16;" :: "r"(saddr), "l"(g));
}
#define CP_COMMIT() asm volatile("cp.async.commit_group;")
#define CP_WAIT1()  asm volatile("cp.async.wait_group 1;")
#define CP_WAIT0()  asm volatile("cp.async.wait_group 0;")

__device__ __forceinline__ void mma_tf32(float* c, unsigned a0, unsigned a1, unsigned a2,
                                         unsigned a3, unsigned b0, unsigned b1) {
    asm volatile(
        "mma.sync.aligned.m16n8k8.row.col.f32.tf32.tf32.f32 "
        "{%0,%1,%2,%3}, {%4,%5,%6,%7}, {%8,%9}, {%0,%1,%2,%3};"
        : "+f"(c[0]), "+f"(c[1]), "+f"(c[2]), "+f"(c[3])
        : "r"(a0), "r"(a1), "r"(a2), "r"(a3), "r"(b0), "r"(b1));
}

// ---------------- repack A: [M][K] row-major -> fragment-major tiles ----------------
// Tile = 128 rows x 16 k. f = wmHalf*1024 + (2*im+ks)*128 + lane*4 + r
// row = wmHalf*64 + im*16 + (r&1)*8 + tr ; col = ks*8 + (r>>1)*4 + tq
template <bool CVT>
__global__ __launch_bounds__(256) void repack_A(const float* __restrict__ in,
                                                float* __restrict__ out, int Kdim) {
    __shared__ float t[2048];
    const int tid = threadIdx.x;
    const int m0 = blockIdx.y * 128, k0 = blockIdx.x * 16;
    const int r = tid >> 1, c = (tid & 1) * 8;
    const float* src = in + (size_t)(m0 + r) * Kdim + k0 + c;
    float4 v0 = ((const float4*)src)[0];
    float4 v1 = ((const float4*)src)[1];
    if (CVT) {
        v0.x = cvt32(v0.x); v0.y = cvt32(v0.y); v0.z = cvt32(v0.z); v0.w = cvt32(v0.w);
        v1.x = cvt32(v1.x); v1.y = cvt32(v1.y); v1.z = cvt32(v1.z); v1.w = cvt32(v1.w);
    }
    *(float4*)&t[r * 16 + c] = v0;
    *(float4*)&t[r * 16 + c + 4] = v1;
    __syncthreads();

    float o[8];
    const int fb = tid * 8;
#pragma unroll
    for (int j = 0; j < 8; j++) {
        const int f = fb + j;
        const int wmHalf = f >> 10;
        const int im = (f >> 8) & 3;
        const int ks = (f >> 7) & 1;
        const int lane = (f >> 2) & 31;
        const int rr = f & 3;
        const int tr = lane >> 2, tq = lane & 3;
        const int row = wmHalf * 64 + im * 16 + (rr & 1) * 8 + tr;
        const int col = ks * 8 + (rr >> 1) * 4 + tq;
        o[j] = t[row * 16 + col];
    }
    float* dst = out + ((size_t)blockIdx.y * (Kdim / 16) + blockIdx.x) * 2048 + fb;
    *(float4*)dst = make_float4(o[0], o[1], o[2], o[3]);
    *(float4*)(dst + 4) = make_float4(o[4], o[5], o[6], o[7]);
}

// ---------------- repack B: W [K][N] -> fragment-major BT tiles (transpose+cvt) ------
// Tile = 128 n x 16 k. f = wq*512 + (2*in+ks)*64 + lane*2 + r
// n = wq*32 + in*8 + tr ; col = ks*8 + r*4 + tq
__global__ __launch_bounds__(256) void repack_B(const float* __restrict__ W,
                                                float* __restrict__ out, int Ndim, int Kdim) {
    __shared__ float t[128 * 17];
    const int tid = threadIdx.x;
    const int n0 = blockIdx.y * 128, k0 = blockIdx.x * 16;
    const int kr = tid >> 4, c = (tid & 15) * 8;
    const float* src = W + (size_t)(k0 + kr) * Ndim + n0 + c;
    float4 v0 = ((const float4*)src)[0];
    float4 v1 = ((const float4*)src)[1];
    t[(c + 0) * 17 + kr] = cvt32(v0.x);
    t[(c + 1) * 17 + kr] = cvt32(v0.y);
    t[(c + 2) * 17 + kr] = cvt32(v0.z);
    t[(c + 3) * 17 + kr] = cvt32(v0.w);
    t[(c + 4) * 17 + kr] = cvt32(v1.x);
    t[(c + 5) * 17 + kr] = cvt32(v1.y);
    t[(c + 6) * 17 + kr] = cvt32(v1.z);
    t[(c + 7) * 17 + kr] = cvt32(v1.w);
    __syncthreads();

    float o[8];
    const int fb = tid * 8;
#pragma unroll
    for (int j = 0; j < 8; j++) {
        const int f = fb + j;
        const int wq = f >> 9;
        const int in_ = (f >> 7) & 3;
        const int ks = (f >> 6) & 1;
        const int lane = (f >> 1) & 31;
        const int rr = f & 1;
        const int tr = lane >> 2, tq = lane & 3;
        const int n = wq * 32 + in_ * 8 + tr;
        const int col = ks * 8 + rr * 4 + tq;
        o[j] = t[n * 17 + col];
    }
    float* dst = out + ((size_t)blockIdx.y * (Kdim / 16) + blockIdx.x) * 2048 + fb;
    *(float4*)dst = make_float4(o[0], o[1], o[2], o[3]);
    *(float4*)(dst + 4) = make_float4(o[4], o[5], o[6], o[7]);
}

// ---------------- fragment-layout TF32 GEMM ----------------
// BM=BN=128, BK=16, 256 threads = 8 warps (2x4), warp tile 64x32.
// Stage = 2048 A floats + 2048 B floats = 16 KB, 3 stages.
#define GEMM_SMEM (3 * 4096 * 4)

template <bool RND>
__global__ __launch_bounds__(256) void gemm_frag(const float* __restrict__ Ap,
                                                 const float* __restrict__ Bp,
                                                 float* __restrict__ C,
                                                 int Ndim, int Kdim) {
    extern __shared__ float smf[];
    const uint32_t smbase = smem_u32(smf);
    const int tid = threadIdx.x;
    const int w = tid >> 5, lane = tid & 31;
    const int wmHalf = w >> 2, wq = w & 3;
    const int tr = lane >> 2, tq = lane & 3;
    const int nch = Kdim / 16;

    const float* Ag = Ap + (size_t)blockIdx.y * nch * 2048 + tid * 8;
    const float* Bg = Bp + (size_t)blockIdx.x * nch * 2048 + tid * 8;
    const uint32_t sAd = smbase + tid * 32;

#pragma unroll
    for (int c = 0; c < 2; c++) {
        const uint32_t off = c * 16384;
        cp_async16(sAd + off, Ag + c * 2048);
        cp_async16(sAd + off + 16, Ag + c * 2048 + 4);
        cp_async16(sAd + off + 8192, Bg + c * 2048);
        cp_async16(sAd + off + 8192 + 16, Bg + c * 2048 + 4);
        CP_COMMIT();
    }

    float acc[4][4][4];
#pragma unroll
    for (int i = 0; i < 4; i++)
#pragma unroll
        for (int j = 0; j < 4; j++)
#pragma unroll
            for (int r = 0; r < 4; r++) acc[i][j][r] = 0.f;

    for (int c = 0; c < nch; c++) {
        CP_WAIT1();
        __syncthreads();

        if (c + 2 < nch) {
            const uint32_t off = ((c + 2) % 3) * 16384;
            cp_async16(sAd + off, Ag + (c + 2) * 2048);
            cp_async16(sAd + off + 16, Ag + (c + 2) * 2048 + 4);
            cp_async16(sAd + off + 8192, Bg + (c + 2) * 2048);
            cp_async16(sAd + off + 8192 + 16, Bg + (c + 2) * 2048 + 4);
        }
        CP_COMMIT();

        const float* As = smf + (c % 3) * 4096 + wmHalf * 1024;
        const float* Bs = smf + (c % 3) * 4096 + 2048 + wq * 512;

#pragma unroll
        for (int ks = 0; ks < 2; ks++) {
            float4 av[4];
            float2 bv[4];
#pragma unroll
            for (int im = 0; im < 4; im++)
                av[im] = *(const float4*)(As + (im * 2 + ks) * 128 + lane * 4);
#pragma unroll
            for (int in_ = 0; in_ < 4; in_++)
                bv[in_] = *(const float2*)(Bs + (in_ * 2 + ks) * 64 + lane * 2);
#pragma unroll
            for (int im = 0; im < 4; im++)
#pragma unroll
                for (int in_ = 0; in_ < 4; in_++)
                    mma_tf32(acc[im][in_],
                             __float_as_uint(av[im].x), __float_as_uint(av[im].y),
                             __float_as_uint(av[im].z), __float_as_uint(av[im].w),
                             __float_as_uint(bv[in_].x), __float_as_uint(bv[in_].y));
        }
    }
    CP_WAIT0();

    const int bm = blockIdx.y * 128, bn = blockIdx.x * 128;
    const int wm = wmHalf * 64, wn = wq * 32;
#pragma unroll
    for (int im = 0; im < 4; im++) {
        const int row0 = bm + wm + im * 16 + tr;
#pragma unroll
        for (int in_ = 0; in_ < 4; in_++) {
            const int col = bn + wn + in_ * 8 + tq * 2;
            float c0 = acc[im][in_][0], c1 = acc[im][in_][1];
            float c2 = acc[im][in_][2], c3 = acc[im][in_][3];
            if (RND) { c0 = cvt32(c0); c1 = cvt32(c1); c2 = cvt32(c2); c3 = cvt32(c3); }
            *(float2*)(C + (size_t)row0 * Ndim + col) = make_float2(c0, c1);
            *(float2*)(C + (size_t)(row0 + 8) * Ndim + col) = make_float2(c2, c3);
        }
    }
}

// ---------------- RoPE: rounds output to tf32, optional scale (for Q) ----------------
__global__ void rope_kernel(float* __restrict__ q, const float* __restrict__ cosf,
                            const float* __restrict__ sinf, int nheads, float outscale) {
    int idx = blockIdx.x * blockDim.x + threadIdx.x;
    int total = BATCH_ * SEQ_ * nheads * 64;
    if (idx >= total) return;
    int i = idx & 63;
    int h = (idx >> 6) % nheads;
    int s = (idx / (64 * nheads)) % SEQ_;
    int b = idx / (64 * nheads * SEQ_);
    float c = cosf[s * 64 + i];
    float sn = sinf[s * 64 + i];
    float* p = q + ((size_t)(b * SEQ_ + s)) * (nheads * HD_) + h * HD_ + 2 * i;
    float xr = p[0], xi = p[1];
    p[0] = cvt32((xr * c - xi * sn) * outscale);
    p[1] = cvt32((xr * sn + xi * c) * outscale);
}

// ---------------- TF32 mma flash attention (inputs pre-rounded/pre-scaled) ----------------
#define QT 128
#define KT 64
#define QS_STRIDE 132
#define KS_STRIDE 132
#define VS_STRIDE 136
#define PS_STRIDE 68
#define ATTN_SMEM_BYTES ((QT * QS_STRIDE + KT * KS_STRIDE + KT * VS_STRIDE + QT * PS_STRIDE) * 4)

__global__ __launch_bounds__(256) void attn_mma(const float* __restrict__ Q,
                                                const float* __restrict__ K,
                                                const float* __restrict__ V,
                                                float* __restrict__ O) {
    extern __shared__ float sm[];
    float* Qs = sm;
    float* Ks = Qs + QT * QS_STRIDE;
    float* Vs = Ks + KT * KS_STRIDE;
    float* Ps = Vs + KT * VS_STRIDE;

    const int tid = threadIdx.x;
    const int w = tid >> 5, lane = tid & 31;
    const int tr = lane >> 2, tq = lane & 3;
    const int b = blockIdx.z, h = blockIdx.y;
    const int g = h / (NHEADS_ / NKV_);
    const int qb = (int)gridDim.x - 1 - (int)blockIdx.x;
    const int q0 = qb * QT;
    const int wm = w * 16;

    {
        const float* qbase = Q + (size_t)(b * SEQ_ + q0) * DIM_ + h * HD_;
        for (int i = tid; i < QT * 32; i += 256) {
            int r = i >> 5, c4 = (i & 31) * 4;
            *(float4*)&Qs[r * QS_STRIDE + c4] = *(const float4*)(qbase + (size_t)r * DIM_ + c4);
        }
    }

    float m0 = -1e30f, m1 = -1e30f, l0 = 0.f, l1 = 0.f;
    float o[16][4];
#pragma unroll
    for (int j = 0; j < 16; j++)
#pragma unroll
        for (int r = 0; r < 4; r++) o[j][r] = 0.f;

    const float* kbase = K + (size_t)b * SEQ_ * (NKV_ * HD_) + g * HD_;
    const float* vbase = V + (size_t)b * SEQ_ * (NKV_ * HD_) + g * HD_;

    const int nchunk = q0 / KT + 2;
    for (int kb = 0; kb < nchunk; kb++) {
        const int key0 = kb * KT;
        __syncthreads();
        for (int i = tid; i < KT * 32; i += 256) {
            int r = i >> 5, c4 = (i & 31) * 4;
            size_t go = (size_t)(key0 + r) * (NKV_ * HD_) + c4;
            *(float4*)&Ks[r * KS_STRIDE + c4] = *(const float4*)(kbase + go);
            *(float4*)&Vs[r * VS_STRIDE + c4] = *(const float4*)(vbase + go);
        }
        __syncthreads();

        float s[8][4];
#pragma unroll
        for (int in_ = 0; in_ < 8; in_++)
#pragma unroll
            for (int r = 0; r < 4; r++) s[in_][r] = 0.f;

#pragma unroll
        for (int kk = 0; kk < HD_; kk += 8) {
            unsigned a0 = __float_as_uint(Qs[(wm + tr) * QS_STRIDE + kk + tq]);
            unsigned a1 = __float_as_uint(Qs[(wm + tr + 8) * QS_STRIDE + kk + tq]);
            unsigned a2 = __float_as_uint(Qs[(wm + tr) * QS_STRIDE + kk + tq + 4]);
            unsigned a3 = __float_as_uint(Qs[(wm + tr + 8) * QS_STRIDE + kk + tq + 4]);
#pragma unroll
            for (int in_ = 0; in_ < 8; in_++) {
                unsigned b0 = __float_as_uint(Ks[(in_ * 8 + tr) * KS_STRIDE + kk + tq]);
                unsigned b1 = __float_as_uint(Ks[(in_ * 8 + tr) * KS_STRIDE + kk + tq + 4]);
                mma_tf32(s[in_], a0, a1, a2, a3, b0, b1);
            }
        }

        if (key0 + KT - 1 > q0) {
            const int r0 = q0 + wm + tr, r1 = r0 + 8;
#pragma unroll
            for (int in_ = 0; in_ < 8; in_++) {
                const int c = key0 + in_ * 8 + 2 * tq;
                if (c > r0) s[in_][0] = -1e30f;
                if (c + 1 > r0) s[in_][1] = -1e30f;
                if (c > r1) s[in_][2] = -1e30f;
                if (c + 1 > r1) s[in_][3] = -1e30f;
            }
        }

        float mx0 = -1e30f, mx1 = -1e30f;
#pragma unroll
        for (int in_ = 0; in_ < 8; in_++) {
            mx0 = fmaxf(mx0, fmaxf(s[in_][0], s[in_][1]));
            mx1 = fmaxf(mx1, fmaxf(s[in_][2], s[in_][3]));
        }
        mx0 = fmaxf(mx0, __shfl_xor_sync(0xffffffffu, mx0, 1));
        mx0 = fmaxf(mx0, __shfl_xor_sync(0xffffffffu, mx0, 2));
        mx1 = fmaxf(mx1, __shfl_xor_sync(0xffffffffu, mx1, 1));
        mx1 = fmaxf(mx1, __shfl_xor_sync(0xffffffffu, mx1, 2));

        const float nm0 = fmaxf(m0, mx0), nm1 = fmaxf(m1, mx1);
        const float al0 = __expf(m0 - nm0), al1 = __expf(m1 - nm1);
        float sum0 = 0.f, sum1 = 0.f;
#pragma unroll
        for (int in_ = 0; in_ < 8; in_++) {
            s[in_][0] = __expf(s[in_][0] - nm0);
            s[in_][1] = __expf(s[in_][1] - nm0);
            s[in_][2] = __expf(s[in_][2] - nm1);
            s[in_][3] = __expf(s[in_][3] - nm1);
            sum0 += s[in_][0] + s[in_][1];
            sum1 += s[in_][2] + s[in_][3];
        }
        sum0 += __shfl_xor_sync(0xffffffffu, sum0, 1);
        sum0 += __shfl_xor_sync(0xffffffffu, sum0, 2);
        sum1 += __shfl_xor_sync(0xffffffffu, sum1, 1);
        sum1 += __shfl_xor_sync(0xffffffffu, sum1, 2);
        l0 = l0 * al0 + sum0;
        l1 = l1 * al1 + sum1;
        m0 = nm0; m1 = nm1;

#pragma unroll
        for (int j = 0; j < 16; j++) {
            o[j][0] *= al0; o[j][1] *= al0;
            o[j][2] *= al1; o[j][3] *= al1;
        }

#pragma unroll
        for (int in_ = 0; in_ < 8; in_++) {
            const int c = in_ * 8 + 2 * tq;
            Ps[(wm + tr) * PS_STRIDE + c] = cvt32(s[in_][0]);
            Ps[(wm + tr) * PS_STRIDE + c + 1] = cvt32(s[in_][1]);
            Ps[(wm + tr + 8) * PS_STRIDE + c] = cvt32(s[in_][2]);
            Ps[(wm + tr + 8) * PS_STRIDE + c + 1] = cvt32(s[in_][3]);
        }
        __syncwarp();

#pragma unroll
        for (int kk = 0; kk < KT; kk += 8) {
            unsigned a0 = __float_as_uint(Ps[(wm + tr) * PS_STRIDE + kk + tq]);
            unsigned a1 = __float_as_uint(Ps[(wm + tr + 8) * PS_STRIDE + kk + tq]);
            unsigned a2 = __float_as_uint(Ps[(wm + tr) * PS_STRIDE + kk + tq + 4]);
            unsigned a3 = __float_as_uint(Ps[(wm + tr + 8) * PS_STRIDE + kk + tq + 4]);
#pragma unroll
            for (int j = 0; j < 16; j++) {
                unsigned b0 = __float_as_uint(Vs[(kk + tq) * VS_STRIDE + j * 8 + tr]);
                unsigned b1 = __float_as_uint(Vs[(kk + tq + 4) * VS_STRIDE + j * 8 + tr]);
                mma_tf32(o[j], a0, a1, a2, a3, b0, b1);
            }
        }
    }

    const float inv0 = 1.f / l0, inv1 = 1.f / l1;
    float* obase = O + (size_t)(b * SEQ_ + q0) * DIM_ + h * HD_;
#pragma unroll
    for (int j = 0; j < 16; j++) {
        const int c = j * 8 + 2 * tq;
        *(float2*)(obase + (size_t)(wm + tr) * DIM_ + c) =
            make_float2(cvt32(o[j][0] * inv0), cvt32(o[j][1] * inv0));
        *(float2*)(obase + (size_t)(wm + tr + 8) * DIM_ + c) =
            make_float2(cvt32(o[j][2] * inv1), cvt32(o[j][3] * inv1));
    }
}

// ---------------- launch ----------------
extern "C" void kernel_launch(void* const* d_in, const int* in_sizes, int n_in,
                              void* d_out, int out_size) {
    const float* x = (const float*)d_in[0];
    const float* fcos = (const float*)d_in[1];
    const float* fsin = (const float*)d_in[2];
    const float* Wq = (const float*)d_in[3];
    const float* Wk = (const float*)d_in[4];
    const float* Wv = (const float*)d_in[5];
    const float* Wo = (const float*)d_in[6];
    float* out = (float*)d_out;

    float *qp, *kp, *vp, *ap, *x32, *wqT, *wkT, *wvT, *woT;
    cudaGetSymbolAddress((void**)&qp, g_q);
    cudaGetSymbolAddress((void**)&kp, g_k);
    cudaGetSymbolAddress((void**)&vp, g_v);
    cudaGetSymbolAddress((void**)&ap, g_attn);
    cudaGetSymbolAddress((void**)&x32, g_x32);
    cudaGetSymbolAddress((void**)&wqT, g_wqT);
    cudaGetSymbolAddress((void**)&wkT, g_wkT);
    cudaGetSymbolAddress((void**)&wvT, g_wvT);
    cudaGetSymbolAddress((void**)&woT, g_woT);

    cudaFuncSetAttribute(attn_mma, cudaFuncAttributeMaxDynamicSharedMemorySize, ATTN_SMEM_BYTES);
    cudaFuncSetAttribute(gemm_frag<false>, cudaFuncAttributeMaxDynamicSharedMemorySize, GEMM_SMEM);
    cudaFuncSetAttribute(gemm_frag<true>, cudaFuncAttributeMaxDynamicSharedMemorySize, GEMM_SMEM);

    // prepass: repack x (with tf32 round) and all weights into fragment layout
    repack_A<true><<<dim3(DIM_ / 16, M_ / 128), 256>>>(x, x32, DIM_);
    repack_B<<<dim3(DIM_ / 16, DIM_ / 128), 256>>>(Wq, wqT, DIM_, DIM_);
    repack_B<<<dim3(DIM_ / 16, (NKV_ * HD_) / 128), 256>>>(Wk, wkT, NKV_ * HD_, DIM_);
    repack_B<<<dim3(DIM_ / 16, (NKV_ * HD_) / 128), 256>>>(Wv, wvT, NKV_ * HD_, DIM_);
    repack_B<<<dim3(DIM_ / 16, DIM_ / 128), 256>>>(Wo, woT, DIM_, DIM_);

    // projections (V rounds output for attention staging)
    gemm_frag<false><<<dim3(DIM_ / 128, M_ / 128), 256, GEMM_SMEM>>>(x32, wqT, qp, DIM_, DIM_);
    gemm_frag<false><<<dim3((NKV_ * HD_) / 128, M_ / 128), 256, GEMM_SMEM>>>(x32, wkT, kp, NKV_ * HD_, DIM_);
    gemm_frag<true><<<dim3((NKV_ * HD_) / 128, M_ / 128), 256, GEMM_SMEM>>>(x32, wvT, vp, NKV_ * HD_, DIM_);

    // RoPE (rounds; Q pre-scaled by 1/sqrt(HD))
    {
        int totq = BATCH_ * SEQ_ * NHEADS_ * 64;
        rope_kernel<<<(totq + 255) / 256, 256>>>(qp, fcos, fsin, NHEADS_, 0.08838834764831845f);
        int totk = BATCH_ * SEQ_ * NKV_ * 64;
        rope_kernel<<<(totk + 255) / 256, 256>>>(kp, fcos, fsin, NKV_, 1.0f);
    }

    // attention
    {
        dim3 grid(SEQ_ / QT, NHEADS_, BATCH_);
        attn_mma<<<grid, 256, ATTN_SMEM_BYTES>>>(qp, kp, vp, ap);
    }

    // repack attention output (already tf32-rounded) into fragment layout, reuse g_x32
    repack_A<false><<<dim3(DIM_ / 16, M_ / 128), 256>>>(ap, x32, DIM_);

    // output projection
    gemm_frag<false><<<dim3(DIM_ / 128, M_ / 128), 256, GEMM_SMEM>>>(x32, woT, out, DIM_, DIM_);
}

// round 13
// speedup vs baseline: 6.6373x; 1.0481x over previous
#include <cuda_runtime.h>
#include <math.h>
#include <stdint.h>

#define DIM_ 2048
#define SEQ_ 2048
#define BATCH_ 2
#define NHEADS_ 16
#define NKV_ 4
#define HD_ 128
#define M_ (BATCH_ * SEQ_)   // 4096

// ---------------- scratch ----------------
__device__ float g_q[(size_t)M_ * DIM_];
__device__ float g_k[(size_t)M_ * (NKV_ * HD_)];
__device__ float g_v[(size_t)M_ * (NKV_ * HD_)];
__device__ float g_attn[(size_t)M_ * DIM_];
__device__ float g_x32[(size_t)M_ * DIM_];              // fragment-packed A (x, later attn)
__device__ float g_wqT[(size_t)DIM_ * DIM_];            // fragment-packed B
__device__ float g_wkT[(size_t)(NKV_ * HD_) * DIM_];
__device__ float g_wvT[(size_t)(NKV_ * HD_) * DIM_];
__device__ float g_woT[(size_t)DIM_ * DIM_];

__device__ __forceinline__ unsigned f2tf32(float f) {
    unsigned u;
    asm("cvt.rna.tf32.f32 %0, %1;" : "=r"(u) : "f"(f));
    return u;
}
__device__ __forceinline__ float cvt32(float f) { return __uint_as_float(f2tf32(f)); }

__device__ __forceinline__ uint32_t smem_u32(const void* p) {
    uint32_t a;
    asm("{ .reg .u64 t; cvta.to.shared.u64 t, %1; cvt.u32.u64 %0, t; }" : "=r"(a) : "l"(p));
    return a;
}
__device__ __forceinline__ void cp_async16(uint32_t saddr, const void* g) {
    asm volatile("cp.async.cg.shared.global [%0], [%1], 16;" :: "r"(saddr), "l"(g));
}
#define CP_COMMIT() asm volatile("cp.async.commit_group;")
#define CP_WAIT1()  asm volatile("cp.async.wait_group 1;")
#define CP_WAIT0()  asm volatile("cp.async.wait_group 0;")

__device__ __forceinline__ void mma_tf32(float* c, unsigned a0, unsigned a1, unsigned a2,
                                         unsigned a3, unsigned b0, unsigned b1) {
    asm volatile(
        "mma.sync.aligned.m16n8k8.row.col.f32.tf32.tf32.f32 "
        "{%0,%1,%2,%3}, {%4,%5,%6,%7}, {%8,%9}, {%0,%1,%2,%3};"
        : "+f"(c[0]), "+f"(c[1]), "+f"(c[2]), "+f"(c[3])
        : "r"(a0), "r"(a1), "r"(a2), "r"(a3), "r"(b0), "r"(b1));
}

// ---------------- repack A: [M][K] row-major -> fragment-major tiles ----------------
template <bool CVT>
__global__ __launch_bounds__(256) void repack_A(const float* __restrict__ in,
                                                float* __restrict__ out, int Kdim) {
    __shared__ float t[2048];
    const int tid = threadIdx.x;
    const int m0 = blockIdx.y * 128, k0 = blockIdx.x * 16;
    const int r = tid >> 1, c = (tid & 1) * 8;
    const float* src = in + (size_t)(m0 + r) * Kdim + k0 + c;
    float4 v0 = ((const float4*)src)[0];
    float4 v1 = ((const float4*)src)[1];
    if (CVT) {
        v0.x = cvt32(v0.x); v0.y = cvt32(v0.y); v0.z = cvt32(v0.z); v0.w = cvt32(v0.w);
        v1.x = cvt32(v1.x); v1.y = cvt32(v1.y); v1.z = cvt32(v1.z); v1.w = cvt32(v1.w);
    }
    *(float4*)&t[r * 16 + c] = v0;
    *(float4*)&t[r * 16 + c + 4] = v1;
    __syncthreads();

    float o[8];
    const int fb = tid * 8;
#pragma unroll
    for (int j = 0; j < 8; j++) {
        const int f = fb + j;
        const int wmHalf = f >> 10;
        const int im = (f >> 8) & 3;
        const int ks = (f >> 7) & 1;
        const int lane = (f >> 2) & 31;
        const int rr = f & 3;
        const int tr = lane >> 2, tq = lane & 3;
        const int row = wmHalf * 64 + im * 16 + (rr & 1) * 8 + tr;
        const int col = ks * 8 + (rr >> 1) * 4 + tq;
        o[j] = t[row * 16 + col];
    }
    float* dst = out + ((size_t)blockIdx.y * (Kdim / 16) + blockIdx.x) * 2048 + fb;
    *(float4*)dst = make_float4(o[0], o[1], o[2], o[3]);
    *(float4*)(dst + 4) = make_float4(o[4], o[5], o[6], o[7]);
}

// ---------------- repack B: W [K][N] -> fragment-major BT tiles (transpose+cvt) ------
__global__ __launch_bounds__(256) void repack_B(const float* __restrict__ W,
                                                float* __restrict__ out, int Ndim, int Kdim) {
    __shared__ float t[128 * 17];
    const int tid = threadIdx.x;
    const int n0 = blockIdx.y * 128, k0 = blockIdx.x * 16;
    const int kr = tid >> 4, c = (tid & 15) * 8;
    const float* src = W + (size_t)(k0 + kr) * Ndim + n0 + c;
    float4 v0 = ((const float4*)src)[0];
    float4 v1 = ((const float4*)src)[1];
    t[(c + 0) * 17 + kr] = cvt32(v0.x);
    t[(c + 1) * 17 + kr] = cvt32(v0.y);
    t[(c + 2) * 17 + kr] = cvt32(v0.z);
    t[(c + 3) * 17 + kr] = cvt32(v0.w);
    t[(c + 4) * 17 + kr] = cvt32(v1.x);
    t[(c + 5) * 17 + kr] = cvt32(v1.y);
    t[(c + 6) * 17 + kr] = cvt32(v1.z);
    t[(c + 7) * 17 + kr] = cvt32(v1.w);
    __syncthreads();

    float o[8];
    const int fb = tid * 8;
#pragma unroll
    for (int j = 0; j < 8; j++) {
        const int f = fb + j;
        const int wq = f >> 9;
        const int in_ = (f >> 7) & 3;
        const int ks = (f >> 6) & 1;
        const int lane = (f >> 1) & 31;
        const int rr = f & 1;
        const int tr = lane >> 2, tq = lane & 3;
        const int n = wq * 32 + in_ * 8 + tr;
        const int col = ks * 8 + rr * 4 + tq;
        o[j] = t[n * 17 + col];
    }
    float* dst = out + ((size_t)blockIdx.y * (Kdim / 16) + blockIdx.x) * 2048 + fb;
    *(float4*)dst = make_float4(o[0], o[1], o[2], o[3]);
    *(float4*)(dst + 4) = make_float4(o[4], o[5], o[6], o[7]);
}

// ---------------- fragment-layout TF32 GEMM w/ fused epilogues ----------------
// EPI: 0=none, 1=round, 2=rope+round (K), 3=rope+scale+round (Q)
#define GEMM_SMEM (3 * 4096 * 4)

template <int EPI>
__global__ __launch_bounds__(256) void gemm_frag(const float* __restrict__ Ap,
                                                 const float* __restrict__ Bp,
                                                 float* __restrict__ C,
                                                 int Ndim, int Kdim,
                                                 const float* __restrict__ fcos,
                                                 const float* __restrict__ fsin) {
    extern __shared__ float smf[];
    const uint32_t smbase = smem_u32(smf);
    const int tid = threadIdx.x;
    const int w = tid >> 5, lane = tid & 31;
    const int wmHalf = w >> 2, wq = w & 3;
    const int tr = lane >> 2, tq = lane & 3;
    const int nch = Kdim / 16;

    const float* Ag = Ap + (size_t)blockIdx.y * nch * 2048 + tid * 8;
    const float* Bg = Bp + (size_t)blockIdx.x * nch * 2048 + tid * 8;
    const uint32_t sAd = smbase + tid * 32;

#pragma unroll
    for (int c = 0; c < 2; c++) {
        const uint32_t off = c * 16384;
        cp_async16(sAd + off, Ag + c * 2048);
        cp_async16(sAd + off + 16, Ag + c * 2048 + 4);
        cp_async16(sAd + off + 8192, Bg + c * 2048);
        cp_async16(sAd + off + 8192 + 16, Bg + c * 2048 + 4);
        CP_COMMIT();
    }

    float acc[4][4][4];
#pragma unroll
    for (int i = 0; i < 4; i++)
#pragma unroll
        for (int j = 0; j < 4; j++)
#pragma unroll
            for (int r = 0; r < 4; r++) acc[i][j][r] = 0.f;

    for (int c = 0; c < nch; c++) {
        CP_WAIT1();
        __syncthreads();

        if (c + 2 < nch) {
            const uint32_t off = ((c + 2) % 3) * 16384;
            cp_async16(sAd + off, Ag + (c + 2) * 2048);
            cp_async16(sAd + off + 16, Ag + (c + 2) * 2048 + 4);
            cp_async16(sAd + off + 8192, Bg + (c + 2) * 2048);
            cp_async16(sAd + off + 8192 + 16, Bg + (c + 2) * 2048 + 4);
        }
        CP_COMMIT();

        const float* As = smf + (c % 3) * 4096 + wmHalf * 1024;
        const float* Bs = smf + (c % 3) * 4096 + 2048 + wq * 512;

#pragma unroll
        for (int ks = 0; ks < 2; ks++) {
            float4 av[4];
            float2 bv[4];
#pragma unroll
            for (int im = 0; im < 4; im++)
                av[im] = *(const float4*)(As + (im * 2 + ks) * 128 + lane * 4);
#pragma unroll
            for (int in_ = 0; in_ < 4; in_++)
                bv[in_] = *(const float2*)(Bs + (in_ * 2 + ks) * 64 + lane * 2);
#pragma unroll
            for (int im = 0; im < 4; im++)
#pragma unroll
                for (int in_ = 0; in_ < 4; in_++)
                    mma_tf32(acc[im][in_],
                             __float_as_uint(av[im].x), __float_as_uint(av[im].y),
                             __float_as_uint(av[im].z), __float_as_uint(av[im].w),
                             __float_as_uint(bv[in_].x), __float_as_uint(bv[in_].y));
        }
    }
    CP_WAIT0();

    const int bm = blockIdx.y * 128, bn = blockIdx.x * 128;
    const int wm = wmHalf * 64, wn = wq * 32;
    const float qscale = 0.08838834764831845f;
#pragma unroll
    for (int im = 0; im < 4; im++) {
        const int row0 = bm + wm + im * 16 + tr;
#pragma unroll
        for (int in_ = 0; in_ < 4; in_++) {
            const int col = bn + wn + in_ * 8 + tq * 2;
            float c0 = acc[im][in_][0], c1 = acc[im][in_][1];
            float c2 = acc[im][in_][2], c3 = acc[im][in_][3];
            if (EPI >= 2) {
                const int i = (col & (HD_ - 1)) >> 1;
                const int s0 = row0 & (SEQ_ - 1);
                const int s1 = (row0 + 8) & (SEQ_ - 1);
                const float cA = fcos[s0 * 64 + i], sA = fsin[s0 * 64 + i];
                const float cB = fcos[s1 * 64 + i], sB = fsin[s1 * 64 + i];
                float r0 = c0 * cA - c1 * sA, i0 = c0 * sA + c1 * cA;
                float r1 = c2 * cB - c3 * sB, i1 = c2 * sB + c3 * cB;
                if (EPI == 3) { r0 *= qscale; i0 *= qscale; r1 *= qscale; i1 *= qscale; }
                c0 = cvt32(r0); c1 = cvt32(i0); c2 = cvt32(r1); c3 = cvt32(i1);
            } else if (EPI == 1) {
                c0 = cvt32(c0); c1 = cvt32(c1); c2 = cvt32(c2); c3 = cvt32(c3);
            }
            *(float2*)(C + (size_t)row0 * Ndim + col) = make_float2(c0, c1);
            *(float2*)(C + (size_t)(row0 + 8) * Ndim + col) = make_float2(c2, c3);
        }
    }
}

// ---------------- TF32 mma flash attention v3 ----------------
// Q fragments in registers; K/V double-buffered via cp.async.
#define QT 128
#define KT 64
#define KS_STRIDE 132
#define VS_STRIDE 136
#define PS_STRIDE 68
#define KVST (KT * KS_STRIDE + KT * VS_STRIDE)   // floats per stage = 17152
#define ATTN_SMEM_BYTES ((2 * KVST + QT * PS_STRIDE) * 4)

__global__ __launch_bounds__(256) void attn_mma(const float* __restrict__ Q,
                                                const float* __restrict__ K,
                                                const float* __restrict__ V,
                                                float* __restrict__ O) {
    extern __shared__ float sm[];
    float* Ps = sm + 2 * KVST;

    const int tid = threadIdx.x;
    const int w = tid >> 5, lane = tid & 31;
    const int tr = lane >> 2, tq = lane & 3;
    const int b = blockIdx.z, h = blockIdx.y;
    const int g = h / (NHEADS_ / NKV_);
    const int qb = (int)gridDim.x - 1 - (int)blockIdx.x;
    const int q0 = qb * QT;
    const int wm = w * 16;
    const uint32_t smbase = smem_u32(sm);

    const float* kbase = K + (size_t)b * SEQ_ * (NKV_ * HD_) + g * HD_;
    const float* vbase = V + (size_t)b * SEQ_ * (NKV_ * HD_) + g * HD_;

    // ---- stage Q once (reuse stage-0 region), then lift fragments to registers ----
    {
        const float* qbase = Q + (size_t)(b * SEQ_ + q0) * DIM_ + h * HD_;
        for (int i = tid; i < QT * 32; i += 256) {
            int r = i >> 5, c4 = (i & 31) * 4;
            *(float4*)&sm[r * KS_STRIDE + c4] = *(const float4*)(qbase + (size_t)r * DIM_ + c4);
        }
    }
    __syncthreads();
    float qf[16][4];
#pragma unroll
    for (int ks = 0; ks < 16; ks++) {
        qf[ks][0] = sm[(wm + tr) * KS_STRIDE + ks * 8 + tq];
        qf[ks][1] = sm[(wm + tr + 8) * KS_STRIDE + ks * 8 + tq];
        qf[ks][2] = sm[(wm + tr) * KS_STRIDE + ks * 8 + tq + 4];
        qf[ks][3] = sm[(wm + tr + 8) * KS_STRIDE + ks * 8 + tq + 4];
    }
    __syncthreads();

    const int nchunk = q0 / KT + 2;

    // ---- prologue: async-stage chunk 0 into stage 0 ----
    {
        const uint32_t sb = smbase;
#pragma unroll
        for (int j = 0; j < 8; j++) {
            const int idx = tid + 256 * j;
            const int row = idx >> 5, cop = idx & 31;
            cp_async16(sb + (row * KS_STRIDE + cop * 4) * 4,
                       kbase + (size_t)row * (NKV_ * HD_) + cop * 4);
            cp_async16(sb + (KT * KS_STRIDE + row * VS_STRIDE + cop * 4) * 4,
                       vbase + (size_t)row * (NKV_ * HD_) + cop * 4);
        }
        CP_COMMIT();
    }

    float m0 = -1e30f, m1 = -1e30f, l0 = 0.f, l1 = 0.f;
    float o[16][4];
#pragma unroll
    for (int j = 0; j < 16; j++)
#pragma unroll
        for (int r = 0; r < 4; r++) o[j][r] = 0.f;

    for (int kb = 0; kb < nchunk; kb++) {
        CP_WAIT0();
        __syncthreads();

        // prefetch next chunk into the other stage
        if (kb + 1 < nchunk) {
            const int key1 = (kb + 1) * KT;
            const uint32_t sb = smbase + ((kb + 1) & 1) * KVST * 4;
#pragma unroll
            for (int j = 0; j < 8; j++) {
                const int idx = tid + 256 * j;
                const int row = idx >> 5, cop = idx & 31;
                cp_async16(sb + (row * KS_STRIDE + cop * 4) * 4,
                           kbase + (size_t)(key1 + row) * (NKV_ * HD_) + cop * 4);
                cp_async16(sb + (KT * KS_STRIDE + row * VS_STRIDE + cop * 4) * 4,
                           vbase + (size_t)(key1 + row) * (NKV_ * HD_) + cop * 4);
            }
        }
        CP_COMMIT();

        const int key0 = kb * KT;
        const float* Ks = sm + (kb & 1) * KVST;
        const float* Vs = Ks + KT * KS_STRIDE;

        // S = Q K^T
        float s[8][4];
#pragma unroll
        for (int in_ = 0; in_ < 8; in_++)
#pragma unroll
            for (int r = 0; r < 4; r++) s[in_][r] = 0.f;

#pragma unroll
        for (int ks = 0; ks < 16; ks++) {
            const unsigned a0 = __float_as_uint(qf[ks][0]);
            const unsigned a1 = __float_as_uint(qf[ks][1]);
            const unsigned a2 = __float_as_uint(qf[ks][2]);
            const unsigned a3 = __float_as_uint(qf[ks][3]);
            const int kk = ks * 8;
#pragma unroll
            for (int in_ = 0; in_ < 8; in_++) {
                unsigned b0 = __float_as_uint(Ks[(in_ * 8 + tr) * KS_STRIDE + kk + tq]);
                unsigned b1 = __float_as_uint(Ks[(in_ * 8 + tr) * KS_STRIDE + kk + tq + 4]);
                mma_tf32(s[in_], a0, a1, a2, a3, b0, b1);
            }
        }

        if (key0 + KT - 1 > q0) {
            const int r0 = q0 + wm + tr, r1 = r0 + 8;
#pragma unroll
            for (int in_ = 0; in_ < 8; in_++) {
                const int c = key0 + in_ * 8 + 2 * tq;
                if (c > r0) s[in_][0] = -1e30f;
                if (c + 1 > r0) s[in_][1] = -1e30f;
                if (c > r1) s[in_][2] = -1e30f;
                if (c + 1 > r1) s[in_][3] = -1e30f;
            }
        }

        float mx0 = -1e30f, mx1 = -1e30f;
#pragma unroll
        for (int in_ = 0; in_ < 8; in_++) {
            mx0 = fmaxf(mx0, fmaxf(s[in_][0], s[in_][1]));
            mx1 = fmaxf(mx1, fmaxf(s[in_][2], s[in_][3]));
        }
        mx0 = fmaxf(mx0, __shfl_xor_sync(0xffffffffu, mx0, 1));
        mx0 = fmaxf(mx0, __shfl_xor_sync(0xffffffffu, mx0, 2));
        mx1 = fmaxf(mx1, __shfl_xor_sync(0xffffffffu, mx1, 1));
        mx1 = fmaxf(mx1, __shfl_xor_sync(0xffffffffu, mx1, 2));

        const float nm0 = fmaxf(m0, mx0), nm1 = fmaxf(m1, mx1);
        const float al0 = __expf(m0 - nm0), al1 = __expf(m1 - nm1);
        float sum0 = 0.f, sum1 = 0.f;
#pragma unroll
        for (int in_ = 0; in_ < 8; in_++) {
            s[in_][0] = __expf(s[in_][0] - nm0);
            s[in_][1] = __expf(s[in_][1] - nm0);
            s[in_][2] = __expf(s[in_][2] - nm1);
            s[in_][3] = __expf(s[in_][3] - nm1);
            sum0 += s[in_][0] + s[in_][1];
            sum1 += s[in_][2] + s[in_][3];
        }
        sum0 += __shfl_xor_sync(0xffffffffu, sum0, 1);
        sum0 += __shfl_xor_sync(0xffffffffu, sum0, 2);
        sum1 += __shfl_xor_sync(0xffffffffu, sum1, 1);
        sum1 += __shfl_xor_sync(0xffffffffu, sum1, 2);
        l0 = l0 * al0 + sum0;
        l1 = l1 * al1 + sum1;
        m0 = nm0; m1 = nm1;

#pragma unroll
        for (int j = 0; j < 16; j++) {
            o[j][0] *= al0; o[j][1] *= al0;
            o[j][2] *= al1; o[j][3] *= al1;
        }

#pragma unroll
        for (int in_ = 0; in_ < 8; in_++) {
            const int c = in_ * 8 + 2 * tq;
            Ps[(wm + tr) * PS_STRIDE + c] = cvt32(s[in_][0]);
            Ps[(wm + tr) * PS_STRIDE + c + 1] = cvt32(s[in_][1]);
            Ps[(wm + tr + 8) * PS_STRIDE + c] = cvt32(s[in_][2]);
            Ps[(wm + tr + 8) * PS_STRIDE + c + 1] = cvt32(s[in_][3]);
        }
        __syncwarp();

#pragma unroll
        for (int kk = 0; kk < KT; kk += 8) {
            unsigned a0 = __float_as_uint(Ps[(wm + tr) * PS_STRIDE + kk + tq]);
            unsigned a1 = __float_as_uint(Ps[(wm + tr + 8) * PS_STRIDE + kk + tq]);
            unsigned a2 = __float_as_uint(Ps[(wm + tr) * PS_STRIDE + kk + tq + 4]);
            unsigned a3 = __float_as_uint(Ps[(wm + tr + 8) * PS_STRIDE + kk + tq + 4]);
#pragma unroll
            for (int j = 0; j < 16; j++) {
                unsigned b0 = __float_as_uint(Vs[(kk + tq) * VS_STRIDE + j * 8 + tr]);
                unsigned b1 = __float_as_uint(Vs[(kk + tq + 4) * VS_STRIDE + j * 8 + tr]);
                mma_tf32(o[j], a0, a1, a2, a3, b0, b1);
            }
        }
    }

    const float inv0 = 1.f / l0, inv1 = 1.f / l1;
    float* obase = O + (size_t)(b * SEQ_ + q0) * DIM_ + h * HD_;
#pragma unroll
    for (int j = 0; j < 16; j++) {
        const int c = j * 8 + 2 * tq;
        *(float2*)(obase + (size_t)(wm + tr) * DIM_ + c) =
            make_float2(cvt32(o[j][0] * inv0), cvt32(o[j][1] * inv0));
        *(float2*)(obase + (size_t)(wm + tr + 8) * DIM_ + c) =
            make_float2(cvt32(o[j][2] * inv1), cvt32(o[j][3] * inv1));
    }
}

// ---------------- launch ----------------
extern "C" void kernel_launch(void* const* d_in, const int* in_sizes, int n_in,
                              void* d_out, int out_size) {
    const float* x = (const float*)d_in[0];
    const float* fcos = (const float*)d_in[1];
    const float* fsin = (const float*)d_in[2];
    const float* Wq = (const float*)d_in[3];
    const float* Wk = (const float*)d_in[4];
    const float* Wv = (const float*)d_in[5];
    const float* Wo = (const float*)d_in[6];
    float* out = (float*)d_out;

    float *qp, *kp, *vp, *ap, *x32, *wqT, *wkT, *wvT, *woT;
    cudaGetSymbolAddress((void**)&qp, g_q);
    cudaGetSymbolAddress((void**)&kp, g_k);
    cudaGetSymbolAddress((void**)&vp, g_v);
    cudaGetSymbolAddress((void**)&ap, g_attn);
    cudaGetSymbolAddress((void**)&x32, g_x32);
    cudaGetSymbolAddress((void**)&wqT, g_wqT);
    cudaGetSymbolAddress((void**)&wkT, g_wkT);
    cudaGetSymbolAddress((void**)&wvT, g_wvT);
    cudaGetSymbolAddress((void**)&woT, g_woT);

    cudaFuncSetAttribute(attn_mma, cudaFuncAttributeMaxDynamicSharedMemorySize, ATTN_SMEM_BYTES);
    cudaFuncSetAttribute(gemm_frag<0>, cudaFuncAttributeMaxDynamicSharedMemorySize, GEMM_SMEM);
    cudaFuncSetAttribute(gemm_frag<1>, cudaFuncAttributeMaxDynamicSharedMemorySize, GEMM_SMEM);
    cudaFuncSetAttribute(gemm_frag<2>, cudaFuncAttributeMaxDynamicSharedMemorySize, GEMM_SMEM);
    cudaFuncSetAttribute(gemm_frag<3>, cudaFuncAttributeMaxDynamicSharedMemorySize, GEMM_SMEM);

    // prepass: repack x (with tf32 round) and all weights into fragment layout
    repack_A<true><<<dim3(DIM_ / 16, M_ / 128), 256>>>(x, x32, DIM_);
    repack_B<<<dim3(DIM_ / 16, DIM_ / 128), 256>>>(Wq, wqT, DIM_, DIM_);
    repack_B<<<dim3(DIM_ / 16, (NKV_ * HD_) / 128), 256>>>(Wk, wkT, NKV_ * HD_, DIM_);
    repack_B<<<dim3(DIM_ / 16, (NKV_ * HD_) / 128), 256>>>(Wv, wvT, NKV_ * HD_, DIM_);
    repack_B<<<dim3(DIM_ / 16, DIM_ / 128), 256>>>(Wo, woT, DIM_, DIM_);

    // projections with fused epilogues: Q=rope+scale, K=rope, V=round
    gemm_frag<3><<<dim3(DIM_ / 128, M_ / 128), 256, GEMM_SMEM>>>(x32, wqT, qp, DIM_, DIM_, fcos, fsin);
    gemm_frag<2><<<dim3((NKV_ * HD_) / 128, M_ / 128), 256, GEMM_SMEM>>>(x32, wkT, kp, NKV_ * HD_, DIM_, fcos, fsin);
    gemm_frag<1><<<dim3((NKV_ * HD_) / 128, M_ / 128), 256, GEMM_SMEM>>>(x32, wvT, vp, NKV_ * HD_, DIM_, nullptr, nullptr);

    // attention
    {
        dim3 grid(SEQ_ / QT, NHEADS_, BATCH_);
        attn_mma<<<grid, 256, ATTN_SMEM_BYTES>>>(qp, kp, vp, ap);
    }

    // repack attention output (already tf32-rounded) into fragment layout, reuse g_x32
    repack_A<false><<<dim3(DIM_ / 16, M_ / 128), 256>>>(ap, x32, DIM_);

    // output projection
    gemm_frag<0><<<dim3(DIM_ / 128, M_ / 128), 256, GEMM_SMEM>>>(x32, woT, out, DIM_, DIM_, nullptr, nullptr);
}

// round 14
// speedup vs baseline: 12.2159x; 1.8405x over previous
#include <cuda_runtime.h>
#include <cuda_fp16.h>
#include <math.h>
#include <stdint.h>

#define DIM_ 2048
#define SEQ_ 2048
#define BATCH_ 2
#define NHEADS_ 16
#define NKV_ 4
#define HD_ 128
#define M_ (BATCH_ * SEQ_)   // 4096

// ---------------- scratch (reinterpreted as needed) ----------------
__device__ float g_q[(size_t)M_ * DIM_];          // fp16 Q [M][2048]
__device__ float g_k[(size_t)M_ * (NKV_ * HD_)];  // fp16 K [M][512]
__device__ float g_v[(size_t)M_ * (NKV_ * HD_)];  // fp16 V^T [B*NKV][128][SEQ]
__device__ float g_attn[(size_t)M_ * DIM_];       // packed attn-out A-frags (uint32)
__device__ float g_x32[(size_t)M_ * DIM_];        // packed x A-frags (uint32)
__device__ float g_wqT[(size_t)DIM_ * DIM_];      // packed B-frags
__device__ float g_wkT[(size_t)(NKV_ * HD_) * DIM_];
__device__ float g_wvT[(size_t)(NKV_ * HD_) * DIM_];
__device__ float g_woT[(size_t)DIM_ * DIM_];

__device__ __forceinline__ uint32_t smem_u32(const void* p) {
    uint32_t a;
    asm("{ .reg .u64 t; cvta.to.shared.u64 t, %1; cvt.u32.u64 %0, t; }" : "=r"(a) : "l"(p));
    return a;
}
__device__ __forceinline__ void cp_async16(uint32_t saddr, const void* g) {
    asm volatile("cp.async.cg.shared.global [%0], [%1], 16;" :: "r"(saddr), "l"(g));
}
#define CP_COMMIT() asm volatile("cp.async.commit_group;")
#define CP_WAIT1()  asm volatile("cp.async.wait_group 1;")
#define CP_WAIT0()  asm volatile("cp.async.wait_group 0;")

__device__ __forceinline__ uint32_t h2pack(float lo, float hi) {
    __half2 h = __floats2half2_rn(lo, hi);
    return *(uint32_t*)&h;
}

__device__ __forceinline__ void mma_h16(float* c, uint32_t a0, uint32_t a1, uint32_t a2,
                                        uint32_t a3, uint32_t b0, uint32_t b1) {
    asm volatile(
        "mma.sync.aligned.m16n8k16.row.col.f32.f16.f16.f32 "
        "{%0,%1,%2,%3}, {%4,%5,%6,%7}, {%8,%9}, {%0,%1,%2,%3};"
        : "+f"(c[0]), "+f"(c[1]), "+f"(c[2]), "+f"(c[3])
        : "r"(a0), "r"(a1), "r"(a2), "r"(a3), "r"(b0), "r"(b1));
}

// ---------------- repack A: fp32 [M][K] -> packed fp16 A-frag tiles (128x16) ----------
// word f in tile: wmHalf*512 + im*128 + lane*4 + r
// row = wmHalf*64+im*16+(r&1)*8+tr ; kpair = (r>>1)*8 + 2*tq
__global__ __launch_bounds__(256) void repack_A_h(const float* __restrict__ in,
                                                  uint32_t* __restrict__ out, int Kdim) {
    __shared__ float t[2048];
    const int tid = threadIdx.x;
    const int m0 = blockIdx.y * 128, k0 = blockIdx.x * 16;
    const int r = tid >> 1, c = (tid & 1) * 8;
    const float* src = in + (size_t)(m0 + r) * Kdim + k0 + c;
    *(float4*)&t[r * 16 + c] = ((const float4*)src)[0];
    *(float4*)&t[r * 16 + c + 4] = ((const float4*)src)[1];
    __syncthreads();

    const int lane = tid & 31;
    const int wmHalf = tid >> 7, im = (tid >> 5) & 3;
    const int tr = lane >> 2, tq = lane & 3;
    uint32_t o[4];
#pragma unroll
    for (int rr = 0; rr < 4; rr++) {
        const int row = wmHalf * 64 + im * 16 + (rr & 1) * 8 + tr;
        const int kb = (rr >> 1) * 8 + 2 * tq;
        o[rr] = h2pack(t[row * 16 + kb], t[row * 16 + kb + 1]);
    }
    uint32_t* dst = out + ((size_t)blockIdx.y * (Kdim / 16) + blockIdx.x) * 1024 + tid * 4;
    *(uint4*)dst = make_uint4(o[0], o[1], o[2], o[3]);
}

// ---------------- repack B: W [K][N] fp32 -> packed fp16 B-frag tiles (128n x 16k) ----
// word f: wq*256 + in*64 + lane*2 + r ;  n = wq*32+in*8+tr ; kpair = r*8 + 2*tq
__global__ __launch_bounds__(256) void repack_B_h(const float* __restrict__ W,
                                                  uint32_t* __restrict__ out, int Ndim, int Kdim) {
    __shared__ float t[128 * 17];
    const int tid = threadIdx.x;
    const int n0 = blockIdx.y * 128, k0 = blockIdx.x * 16;
    const int kr = tid >> 4, c = (tid & 15) * 8;
    const float* src = W + (size_t)(k0 + kr) * Ndim + n0 + c;
    float4 v0 = ((const float4*)src)[0];
    float4 v1 = ((const float4*)src)[1];
    t[(c + 0) * 17 + kr] = v0.x; t[(c + 1) * 17 + kr] = v0.y;
    t[(c + 2) * 17 + kr] = v0.z; t[(c + 3) * 17 + kr] = v0.w;
    t[(c + 4) * 17 + kr] = v1.x; t[(c + 5) * 17 + kr] = v1.y;
    t[(c + 6) * 17 + kr] = v1.z; t[(c + 7) * 17 + kr] = v1.w;
    __syncthreads();

    uint32_t o[4];
#pragma unroll
    for (int j = 0; j < 4; j++) {
        const int f = tid * 4 + j;
        const int wq = f >> 8, in_ = (f >> 6) & 3;
        const int lane = (f >> 1) & 31, rr = f & 1;
        const int tr = lane >> 2, tq = lane & 3;
        const int n = wq * 32 + in_ * 8 + tr;
        const int kb = rr * 8 + 2 * tq;
        o[j] = h2pack(t[n * 17 + kb], t[n * 17 + kb + 1]);
    }
    uint32_t* dst = out + ((size_t)blockIdx.y * (Kdim / 16) + blockIdx.x) * 1024 + tid * 4;
    *(uint4*)dst = make_uint4(o[0], o[1], o[2], o[3]);
}

// ---------------- fp16 fragment GEMM w/ fused epilogues ----------------
// EPI: 0 = fp32 out (O-proj) ; 2 = rope -> fp16 ; 3 = rope+scale -> fp16 ; 4 = V^T fp16
#define GEMM_SMEM (3 * 2048 * 4)

template <int EPI>
__global__ __launch_bounds__(256) void gemm_h(const uint32_t* __restrict__ Ap,
                                              const uint32_t* __restrict__ Bp,
                                              void* __restrict__ Cv,
                                              int Ndim, int Kdim,
                                              const float* __restrict__ fcos,
                                              const float* __restrict__ fsin) {
    extern __shared__ uint32_t smw[];
    const uint32_t smbase = smem_u32(smw);
    const int tid = threadIdx.x;
    const int w = tid >> 5, lane = tid & 31;
    const int wmHalf = w >> 2, wq = w & 3;
    const int tr = lane >> 2, tq = lane & 3;
    const int nch = Kdim / 16;

    const uint32_t* Ag = Ap + (size_t)blockIdx.y * nch * 1024 + tid * 4;
    const uint32_t* Bg = Bp + (size_t)blockIdx.x * nch * 1024 + tid * 4;
    const uint32_t sAd = smbase + tid * 16;

#pragma unroll
    for (int c = 0; c < 2; c++) {
        cp_async16(sAd + c * 8192, Ag + c * 1024);
        cp_async16(sAd + c * 8192 + 4096, Bg + c * 1024);
        CP_COMMIT();
    }

    float acc[4][4][4];
#pragma unroll
    for (int i = 0; i < 4; i++)
#pragma unroll
        for (int j = 0; j < 4; j++)
#pragma unroll
            for (int r = 0; r < 4; r++) acc[i][j][r] = 0.f;

    for (int c = 0; c < nch; c++) {
        CP_WAIT1();
        __syncthreads();
        if (c + 2 < nch) {
            const uint32_t off = ((c + 2) % 3) * 8192;
            cp_async16(sAd + off, Ag + (c + 2) * 1024);
            cp_async16(sAd + off + 4096, Bg + (c + 2) * 1024);
        }
        CP_COMMIT();

        const uint32_t* As = smw + (c % 3) * 2048 + wmHalf * 512;
        const uint32_t* Bs = smw + (c % 3) * 2048 + 1024 + wq * 256;

        uint4 av[4];
        uint2 bv[4];
#pragma unroll
        for (int im = 0; im < 4; im++) av[im] = *(const uint4*)(As + im * 128 + lane * 4);
#pragma unroll
        for (int in_ = 0; in_ < 4; in_++) bv[in_] = *(const uint2*)(Bs + in_ * 64 + lane * 2);
#pragma unroll
        for (int im = 0; im < 4; im++)
#pragma unroll
            for (int in_ = 0; in_ < 4; in_++)
                mma_h16(acc[im][in_], av[im].x, av[im].y, av[im].z, av[im].w,
                        bv[in_].x, bv[in_].y);
    }
    CP_WAIT0();

    const int bm = blockIdx.y * 128, bn = blockIdx.x * 128;
    const int wm = wmHalf * 64, wn = wq * 32;
    const float qscale = 0.08838834764831845f;
#pragma unroll
    for (int im = 0; im < 4; im++) {
        const int row0 = bm + wm + im * 16 + tr;
#pragma unroll
        for (int in_ = 0; in_ < 4; in_++) {
            const int col = bn + wn + in_ * 8 + tq * 2;
            float c0 = acc[im][in_][0], c1 = acc[im][in_][1];
            float c2 = acc[im][in_][2], c3 = acc[im][in_][3];
            if (EPI == 0) {
                float* C = (float*)Cv;
                *(float2*)(C + (size_t)row0 * Ndim + col) = make_float2(c0, c1);
                *(float2*)(C + (size_t)(row0 + 8) * Ndim + col) = make_float2(c2, c3);
            } else if (EPI == 2 || EPI == 3) {
                const int i = (col & (HD_ - 1)) >> 1;
                const int s0 = row0 & (SEQ_ - 1);
                const int s1 = (row0 + 8) & (SEQ_ - 1);
                const float cA = fcos[s0 * 64 + i], sA = fsin[s0 * 64 + i];
                const float cB = fcos[s1 * 64 + i], sB = fsin[s1 * 64 + i];
                float r0 = c0 * cA - c1 * sA, i0 = c0 * sA + c1 * cA;
                float r1 = c2 * cB - c3 * sB, i1 = c2 * sB + c3 * cB;
                if (EPI == 3) { r0 *= qscale; i0 *= qscale; r1 *= qscale; i1 *= qscale; }
                uint32_t* C = (uint32_t*)Cv;
                C[((size_t)row0 * Ndim + col) >> 1] = h2pack(r0, i0);
                C[((size_t)(row0 + 8) * Ndim + col) >> 1] = h2pack(r1, i1);
            } else {  // EPI 4: V^T fp16 [B*NKV][128][SEQ]
                __half* vt = (__half*)Cv;
                const int g = col >> 7, d = col & 127;
                const int b0_ = row0 >> 11, s0 = row0 & 2047;
                const int b1_ = (row0 + 8) >> 11, s1 = (row0 + 8) & 2047;
                vt[(((size_t)b0_ * NKV_ + g) * 128 + d) * SEQ_ + s0] = __float2half(c0);
                vt[(((size_t)b0_ * NKV_ + g) * 128 + d + 1) * SEQ_ + s0] = __float2half(c1);
                vt[(((size_t)b1_ * NKV_ + g) * 128 + d) * SEQ_ + s1] = __float2half(c2);
                vt[(((size_t)b1_ * NKV_ + g) * 128 + d + 1) * SEQ_ + s1] = __float2half(c3);
            }
        }
    }
}

// ---------------- fp16 mma flash attention ----------------
// QT=128 rows, KT=64 keys, 8 warps (warp = 16 rows, full width). P stays in registers.
#define QT 128
#define KT 64
#define KSTW 68                     // K row stride in u32 words (64 half2 + pad)
#define VSTW 36                     // V^T row stride in u32 words (32 half2 + pad)
#define KVSTG (KT * KSTW + 128 * VSTW)   // words per stage = 4352+4608 = 8960
#define ATTN_SMEM_BYTES (2 * KVSTG * 4)  // 71680

__global__ __launch_bounds__(256) void attn_h(const __half* __restrict__ Q,
                                              const __half* __restrict__ K,
                                              const __half* __restrict__ Vt,
                                              uint32_t* __restrict__ Opack) {
    extern __shared__ uint32_t smw[];
    const uint32_t smbase = smem_u32(smw);
    const int tid = threadIdx.x;
    const int w = tid >> 5, lane = tid & 31;
    const int tr = lane >> 2, tq = lane & 3;
    const int b = blockIdx.z, h = blockIdx.y;
    const int g = h / (NHEADS_ / NKV_);
    const int qb = (int)gridDim.x - 1 - (int)blockIdx.x;
    const int q0 = qb * QT;
    const int wm = w * 16;

    const __half* kbase = K + (size_t)b * SEQ_ * (NKV_ * HD_) + g * HD_;
    const __half* vtbase = Vt + (((size_t)b * NKV_ + g) * 128) * SEQ_;

    // ---- stage Q tile into stage-0 region, lift fragments to registers ----
    {
        const __half* qbase = Q + (size_t)(b * SEQ_ + q0) * DIM_ + h * HD_;
#pragma unroll
        for (int j = 0; j < 8; j++) {
            const int idx = tid + 256 * j;          // 2048 chunks of 16B
            const int row = idx >> 4, c16 = idx & 15;
            cp_async16(smbase + (row * KSTW + c16 * 4) * 4,
                       qbase + (size_t)row * DIM_ + c16 * 8);
        }
        CP_COMMIT();
        CP_WAIT0();
    }
    __syncthreads();
    uint4 qa[8];
#pragma unroll
    for (int gk = 0; gk < 8; gk++) {
        qa[gk].x = smw[(wm + tr) * KSTW + gk * 8 + tq];
        qa[gk].y = smw[(wm + tr + 8) * KSTW + gk * 8 + tq];
        qa[gk].z = smw[(wm + tr) * KSTW + gk * 8 + tq + 4];
        qa[gk].w = smw[(wm + tr + 8) * KSTW + gk * 8 + tq + 4];
    }
    __syncthreads();

    const int nchunk = q0 / KT + 2;

    // ---- prologue: stage chunk 0 ----
    {
        const uint32_t sb = smbase;
#pragma unroll
        for (int j = 0; j < 4; j++) {   // K: 64 rows x 16 chunks = 1024
            const int idx = tid + 256 * j;
            const int row = idx >> 4, c16 = idx & 15;
            cp_async16(sb + (row * KSTW + c16 * 4) * 4,
                       kbase + (size_t)row * (NKV_ * HD_) + c16 * 8);
        }
#pragma unroll
        for (int j = 0; j < 4; j++) {   // V^T: 128 rows x 8 chunks = 1024
            const int idx = tid + 256 * j;
            const int row = idx >> 3, c16 = idx & 7;
            cp_async16(sb + (KT * KSTW + row * VSTW + c16 * 4) * 4,
                       vtbase + (size_t)row * SEQ_ + c16 * 8);
        }
        CP_COMMIT();
    }

    float m0 = -1e30f, m1 = -1e30f, l0 = 0.f, l1 = 0.f;
    float o[16][4];
#pragma unroll
    for (int j = 0; j < 16; j++)
#pragma unroll
        for (int r = 0; r < 4; r++) o[j][r] = 0.f;

    for (int kb = 0; kb < nchunk; kb++) {
        CP_WAIT0();
        __syncthreads();

        if (kb + 1 < nchunk) {
            const int key1 = (kb + 1) * KT;
            const uint32_t sb = smbase + ((kb + 1) & 1) * KVSTG * 4;
#pragma unroll
            for (int j = 0; j < 4; j++) {
                const int idx = tid + 256 * j;
                const int row = idx >> 4, c16 = idx & 15;
                cp_async16(sb + (row * KSTW + c16 * 4) * 4,
                           kbase + (size_t)(key1 + row) * (NKV_ * HD_) + c16 * 8);
            }
#pragma unroll
            for (int j = 0; j < 4; j++) {
                const int idx = tid + 256 * j;
                const int row = idx >> 3, c16 = idx & 7;
                cp_async16(sb + (KT * KSTW + row * VSTW + c16 * 4) * 4,
                           vtbase + (size_t)row * SEQ_ + key1 + c16 * 8);
            }
        }
        CP_COMMIT();

        const int key0 = kb * KT;
        const uint32_t* Ks = smw + (kb & 1) * KVSTG;
        const uint32_t* Vs = Ks + KT * KSTW;

        // ---- S = Q K^T ----
        float s[8][4];
#pragma unroll
        for (int in_ = 0; in_ < 8; in_++)
#pragma unroll
            for (int r = 0; r < 4; r++) s[in_][r] = 0.f;

#pragma unroll
        for (int gk = 0; gk < 8; gk++) {
#pragma unroll
            for (int in_ = 0; in_ < 8; in_++) {
                const uint32_t* kr = Ks + (in_ * 8 + tr) * KSTW + gk * 8 + tq;
                mma_h16(s[in_], qa[gk].x, qa[gk].y, qa[gk].z, qa[gk].w, kr[0], kr[4]);
            }
        }

        if (key0 + KT - 1 > q0) {
            const int r0 = q0 + wm + tr, r1 = r0 + 8;
#pragma unroll
            for (int in_ = 0; in_ < 8; in_++) {
                const int c = key0 + in_ * 8 + 2 * tq;
                if (c > r0) s[in_][0] = -1e30f;
                if (c + 1 > r0) s[in_][1] = -1e30f;
                if (c > r1) s[in_][2] = -1e30f;
                if (c + 1 > r1) s[in_][3] = -1e30f;
            }
        }

        // ---- online softmax ----
        float mx0 = -1e30f, mx1 = -1e30f;
#pragma unroll
        for (int in_ = 0; in_ < 8; in_++) {
            mx0 = fmaxf(mx0, fmaxf(s[in_][0], s[in_][1]));
            mx1 = fmaxf(mx1, fmaxf(s[in_][2], s[in_][3]));
        }
        mx0 = fmaxf(mx0, __shfl_xor_sync(0xffffffffu, mx0, 1));
        mx0 = fmaxf(mx0, __shfl_xor_sync(0xffffffffu, mx0, 2));
        mx1 = fmaxf(mx1, __shfl_xor_sync(0xffffffffu, mx1, 1));
        mx1 = fmaxf(mx1, __shfl_xor_sync(0xffffffffu, mx1, 2));

        const float nm0 = fmaxf(m0, mx0), nm1 = fmaxf(m1, mx1);
        const float al0 = __expf(m0 - nm0), al1 = __expf(m1 - nm1);
        float sum0 = 0.f, sum1 = 0.f;
#pragma unroll
        for (int in_ = 0; in_ < 8; in_++) {
            s[in_][0] = __expf(s[in_][0] - nm0);
            s[in_][1] = __expf(s[in_][1] - nm0);
            s[in_][2] = __expf(s[in_][2] - nm1);
            s[in_][3] = __expf(s[in_][3] - nm1);
            sum0 += s[in_][0] + s[in_][1];
            sum1 += s[in_][2] + s[in_][3];
        }
        sum0 += __shfl_xor_sync(0xffffffffu, sum0, 1);
        sum0 += __shfl_xor_sync(0xffffffffu, sum0, 2);
        sum1 += __shfl_xor_sync(0xffffffffu, sum1, 1);
        sum1 += __shfl_xor_sync(0xffffffffu, sum1, 2);
        l0 = l0 * al0 + sum0;
        l1 = l1 * al1 + sum1;
        m0 = nm0; m1 = nm1;

#pragma unroll
        for (int j = 0; j < 16; j++) {
            o[j][0] *= al0; o[j][1] *= al0;
            o[j][2] *= al1; o[j][3] *= al1;
        }

        // ---- pack P into m16n8k16 A-fragments (register-only!) ----
        uint4 pa[4];
#pragma unroll
        for (int gp = 0; gp < 4; gp++) {
            pa[gp].x = h2pack(s[2 * gp][0], s[2 * gp][1]);
            pa[gp].y = h2pack(s[2 * gp][2], s[2 * gp][3]);
            pa[gp].z = h2pack(s[2 * gp + 1][0], s[2 * gp + 1][1]);
            pa[gp].w = h2pack(s[2 * gp + 1][2], s[2 * gp + 1][3]);
        }

        // ---- O += P V ----
#pragma unroll
        for (int gp = 0; gp < 4; gp++) {
#pragma unroll
            for (int j = 0; j < 16; j++) {
                const uint32_t* vr = Vs + (j * 8 + tr) * VSTW + gp * 8 + tq;
                mma_h16(o[j], pa[gp].x, pa[gp].y, pa[gp].z, pa[gp].w, vr[0], vr[4]);
            }
        }
    }

    // ---- epilogue: write packed A-fragments for the O-projection ----
    const float inv0 = 1.f / l0, inv1 = 1.f / l1;
    const int mtile = b * (SEQ_ / 128) + qb;
    const int wmHalf = w >> 2, im = w & 3;
#pragma unroll
    for (int jp = 0; jp < 8; jp++) {
        const int j0 = 2 * jp, j1 = 2 * jp + 1;
        uint4 ov;
        ov.x = h2pack(o[j0][0] * inv0, o[j0][1] * inv0);
        ov.y = h2pack(o[j0][2] * inv1, o[j0][3] * inv1);
        ov.z = h2pack(o[j1][0] * inv0, o[j1][1] * inv0);
        ov.w = h2pack(o[j1][2] * inv1, o[j1][3] * inv1);
        uint32_t* dst = Opack + ((size_t)mtile * (DIM_ / 16) + h * 8 + jp) * 1024 +
                        wmHalf * 512 + im * 128 + lane * 4;
        *(uint4*)dst = ov;
    }
}

// ---------------- launch ----------------
extern "C" void kernel_launch(void* const* d_in, const int* in_sizes, int n_in,
                              void* d_out, int out_size) {
    const float* x = (const float*)d_in[0];
    const float* fcos = (const float*)d_in[1];
    const float* fsin = (const float*)d_in[2];
    const float* Wq = (const float*)d_in[3];
    const float* Wk = (const float*)d_in[4];
    const float* Wv = (const float*)d_in[5];
    const float* Wo = (const float*)d_in[6];
    float* out = (float*)d_out;

    void *qp, *kp, *vp, *ap, *xp, *wq, *wk, *wv, *wo;
    cudaGetSymbolAddress(&qp, g_q);
    cudaGetSymbolAddress(&kp, g_k);
    cudaGetSymbolAddress(&vp, g_v);
    cudaGetSymbolAddress(&ap, g_attn);
    cudaGetSymbolAddress(&xp, g_x32);
    cudaGetSymbolAddress(&wq, g_wqT);
    cudaGetSymbolAddress(&wk, g_wkT);
    cudaGetSymbolAddress(&wv, g_wvT);
    cudaGetSymbolAddress(&wo, g_woT);

    cudaFuncSetAttribute(attn_h, cudaFuncAttributeMaxDynamicSharedMemorySize, ATTN_SMEM_BYTES);
    cudaFuncSetAttribute(gemm_h<0>, cudaFuncAttributeMaxDynamicSharedMemorySize, GEMM_SMEM);
    cudaFuncSetAttribute(gemm_h<2>, cudaFuncAttributeMaxDynamicSharedMemorySize, GEMM_SMEM);
    cudaFuncSetAttribute(gemm_h<3>, cudaFuncAttributeMaxDynamicSharedMemorySize, GEMM_SMEM);
    cudaFuncSetAttribute(gemm_h<4>, cudaFuncAttributeMaxDynamicSharedMemorySize, GEMM_SMEM);

    // prepass: pack x and weights into fp16 fragment tiles
    repack_A_h<<<dim3(DIM_ / 16, M_ / 128), 256>>>(x, (uint32_t*)xp, DIM_);
    repack_B_h<<<dim3(DIM_ / 16, DIM_ / 128), 256>>>(Wq, (uint32_t*)wq, DIM_, DIM_);
    repack_B_h<<<dim3(DIM_ / 16, (NKV_ * HD_) / 128), 256>>>(Wk, (uint32_t*)wk, NKV_ * HD_, DIM_);
    repack_B_h<<<dim3(DIM_ / 16, (NKV_ * HD_) / 128), 256>>>(Wv, (uint32_t*)wv, NKV_ * HD_, DIM_);
    repack_B_h<<<dim3(DIM_ / 16, DIM_ / 128), 256>>>(Wo, (uint32_t*)wo, DIM_, DIM_);

    // projections: Q = rope+scale fp16, K = rope fp16, V = transposed fp16
    gemm_h<3><<<dim3(DIM_ / 128, M_ / 128), 256, GEMM_SMEM>>>(
        (const uint32_t*)xp, (const uint32_t*)wq, qp, DIM_, DIM_, fcos, fsin);
    gemm_h<2><<<dim3((NKV_ * HD_) / 128, M_ / 128), 256, GEMM_SMEM>>>(
        (const uint32_t*)xp, (const uint32_t*)wk, kp, NKV_ * HD_, DIM_, fcos, fsin);
    gemm_h<4><<<dim3((NKV_ * HD_) / 128, M_ / 128), 256, GEMM_SMEM>>>(
        (const uint32_t*)xp, (const uint32_t*)wv, vp, NKV_ * HD_, DIM_, nullptr, nullptr);

    // attention (writes packed A-frags directly)
    {
        dim3 grid(SEQ_ / QT, NHEADS_, BATCH_);
        attn_h<<<grid, 256, ATTN_SMEM_BYTES>>>((const __half*)qp, (const __half*)kp,
                                               (const __half*)vp, (uint32_t*)ap);
    }

    // output projection (fp32 out)
    gemm_h<0><<<dim3(DIM_ / 128, M_ / 128), 256, GEMM_SMEM>>>(
        (const uint32_t*)ap, (const uint32_t*)wo, out, DIM_, DIM_, nullptr, nullptr);
}

// round 17
// speedup vs baseline: 12.9651x; 1.0613x over previous
#include <cuda_runtime.h>
#include <cuda_fp16.h>
#include <math.h>
#include <stdint.h>

#define DIM_ 2048
#define SEQ_ 2048
#define BATCH_ 2
#define NHEADS_ 16
#define NKV_ 4
#define HD_ 128
#define M_ (BATCH_ * SEQ_)   // 4096

// ---------------- scratch (word = uint32 = half2) ----------------
__device__ float g_q[(size_t)M_ * DIM_];          // Q A-frag words [b][qtile][h][w][gk][lane][reg]
__device__ float g_k[(size_t)M_ * (NKV_ * HD_)];  // K B-frag words [bg][keytile][dchunk][1024]
__device__ float g_v[(size_t)M_ * (NKV_ * HD_)];  // V B-frag words [bg][kchunk][1024]
__device__ float g_attn[(size_t)M_ * DIM_];       // attn-out A-frag tiles
__device__ float g_x32[(size_t)M_ * DIM_];        // x A-frag tiles
__device__ float g_wqT[(size_t)DIM_ * DIM_];      // combined QKV B-frag tiles (12 nblks)
__device__ float g_woT[(size_t)DIM_ * DIM_];      // Wo B-frag tiles (8 nblks)

__device__ __forceinline__ uint32_t smem_u32(const void* p) {
    uint32_t a;
    asm("{ .reg .u64 t; cvta.to.shared.u64 t, %1; cvt.u32.u64 %0, t; }" : "=r"(a) : "l"(p));
    return a;
}
__device__ __forceinline__ void cp_async16(uint32_t saddr, const void* g) {
    asm volatile("cp.async.cg.shared.global [%0], [%1], 16;" :: "r"(saddr), "l"(g));
}
#define CP_COMMIT() asm volatile("cp.async.commit_group;")
#define CP_WAIT1()  asm volatile("cp.async.wait_group 1;")
#define CP_WAIT0()  asm volatile("cp.async.wait_group 0;")

__device__ __forceinline__ uint32_t h2pack(float lo, float hi) {
    __half2 h = __floats2half2_rn(lo, hi);
    return *(uint32_t*)&h;
}
__device__ __forceinline__ void mma_h16(float* c, uint32_t a0, uint32_t a1, uint32_t a2,
                                        uint32_t a3, uint32_t b0, uint32_t b1) {
    asm volatile(
        "mma.sync.aligned.m16n8k16.row.col.f32.f16.f16.f32 "
        "{%0,%1,%2,%3}, {%4,%5,%6,%7}, {%8,%9}, {%0,%1,%2,%3};"
        : "+f"(c[0]), "+f"(c[1]), "+f"(c[2]), "+f"(c[3])
        : "r"(a0), "r"(a1), "r"(a2), "r"(a3), "r"(b0), "r"(b1));
}

// ---------------- repack A: fp32 [M][K] -> packed fp16 A-frag tiles (128x16) ----------
__global__ __launch_bounds__(256) void repack_A_h(const float* __restrict__ in,
                                                  uint32_t* __restrict__ out, int Kdim) {
    __shared__ float t[2048];
    const int tid = threadIdx.x;
    const int m0 = blockIdx.y * 128, k0 = blockIdx.x * 16;
    const int r = tid >> 1, c = (tid & 1) * 8;
    const float* src = in + (size_t)(m0 + r) * Kdim + k0 + c;
    *(float4*)&t[r * 16 + c] = ((const float4*)src)[0];
    *(float4*)&t[r * 16 + c + 4] = ((const float4*)src)[1];
    __syncthreads();

    const int lane = tid & 31;
    const int wmHalf = tid >> 7, im = (tid >> 5) & 3;
    const int tr = lane >> 2, tq = lane & 3;
    uint32_t o[4];
#pragma unroll
    for (int rr = 0; rr < 4; rr++) {
        const int row = wmHalf * 64 + im * 16 + (rr & 1) * 8 + tr;
        const int kb = (rr >> 1) * 8 + 2 * tq;
        o[rr] = h2pack(t[row * 16 + kb], t[row * 16 + kb + 1]);
    }
    uint32_t* dst = out + ((size_t)blockIdx.y * (Kdim / 16) + blockIdx.x) * 1024 + tid * 4;
    *(uint4*)dst = make_uint4(o[0], o[1], o[2], o[3]);
}

// ---------------- repack B2: W [K][N] -> 256n x 16k B-frag tiles ----------------
// word f = wq*512 + in_*64 + lane*2 + r ; n = wq*64+in_*8+tr ; kpair = r*8+2tq
__global__ __launch_bounds__(256) void repack_B2(const float* __restrict__ W,
                                                 uint32_t* __restrict__ out,
                                                 int Ndim, int nblkOff) {
    __shared__ float t[16 * 257];
    const int tid = threadIdx.x;
    const int n0 = blockIdx.y * 256, k0 = blockIdx.x * 16;
    const int kr = tid >> 4, c0 = (tid & 15) * 16;
    const float* src = W + (size_t)(k0 + kr) * Ndim + n0 + c0;
#pragma unroll
    for (int i = 0; i < 4; i++) {
        float4 v = ((const float4*)src)[i];
        t[kr * 257 + c0 + i * 4 + 0] = v.x;
        t[kr * 257 + c0 + i * 4 + 1] = v.y;
        t[kr * 257 + c0 + i * 4 + 2] = v.z;
        t[kr * 257 + c0 + i * 4 + 3] = v.w;
    }
    __syncthreads();

    uint32_t o[8];
#pragma unroll
    for (int j = 0; j < 8; j++) {
        const int f = tid * 8 + j;
        const int wq = f >> 9, in_ = (f >> 6) & 7;
        const int lane = (f >> 1) & 31, rr = f & 1;
        const int tr = lane >> 2, tq = lane & 3;
        const int n = wq * 64 + in_ * 8 + tr;
        const int k = rr * 8 + 2 * tq;
        o[j] = h2pack(t[k * 257 + n], t[(k + 1) * 257 + n]);
    }
    uint32_t* dst = out + ((size_t)(nblkOff + blockIdx.y) * 128 + blockIdx.x) * 2048 + tid * 8;
    *(uint4*)dst = make_uint4(o[0], o[1], o[2], o[3]);
    *(uint4*)(dst + 4) = make_uint4(o[4], o[5], o[6], o[7]);
}

// ---------------- fp16 GEMM: 128x256 block, warp 64x64, K=2048 ----------------
// EPI 0: fp32 out ; EPI 5: fused QKV epilogue (Q rope+scale frag / K rope frag / V frag)
template <int EPI>
__global__ __launch_bounds__(256) void gemm_h2(const uint32_t* __restrict__ Ap,
                                               const uint32_t* __restrict__ Bp,
                                               void* __restrict__ out0,
                                               void* __restrict__ out1,
                                               void* __restrict__ out2,
                                               const float* __restrict__ fcos,
                                               const float* __restrict__ fsin) {
    __shared__ uint32_t smw[3 * 3072];
    const uint32_t smbase = smem_u32(smw);
    const int tid = threadIdx.x;
    const int w = tid >> 5, lane = tid & 31;
    const int wmHalf = w >> 2, wq = w & 3;
    const int tr = lane >> 2, tq = lane & 3;
    const int nch = 128;   // K = 2048

    const uint32_t* Ag = Ap + (size_t)blockIdx.y * nch * 1024 + tid * 4;
    const uint32_t* Bg = Bp + (size_t)blockIdx.x * nch * 2048 + tid * 4;

#pragma unroll
    for (int c = 0; c < 2; c++) {
        const uint32_t so = smbase + (c * 3072 + tid * 4) * 4;
        cp_async16(so, Ag + c * 1024);
        cp_async16(so + 1024 * 4, Bg + c * 2048);
        cp_async16(so + 2048 * 4, Bg + c * 2048 + 1024);
        CP_COMMIT();
    }

    float acc[4][8][4];
#pragma unroll
    for (int i = 0; i < 4; i++)
#pragma unroll
        for (int j = 0; j < 8; j++)
#pragma unroll
            for (int r = 0; r < 4; r++) acc[i][j][r] = 0.f;

    for (int c = 0; c < nch; c++) {
        CP_WAIT1();
        __syncthreads();
        if (c + 2 < nch) {
            const uint32_t so = smbase + (((c + 2) % 3) * 3072 + tid * 4) * 4;
            cp_async16(so, Ag + (c + 2) * 1024);
            cp_async16(so + 1024 * 4, Bg + (c + 2) * 2048);
            cp_async16(so + 2048 * 4, Bg + (c + 2) * 2048 + 1024);
        }
        CP_COMMIT();

        const uint32_t* As = smw + (c % 3) * 3072 + wmHalf * 512;
        const uint32_t* Bs = smw + (c % 3) * 3072 + 1024 + wq * 512;

        uint4 av[4];
        uint2 bv[8];
#pragma unroll
        for (int im = 0; im < 4; im++) av[im] = *(const uint4*)(As + im * 128 + lane * 4);
#pragma unroll
        for (int in_ = 0; in_ < 8; in_++) bv[in_] = *(const uint2*)(Bs + in_ * 64 + lane * 2);
#pragma unroll
        for (int im = 0; im < 4; im++)
#pragma unroll
            for (int in_ = 0; in_ < 8; in_++)
                mma_h16(acc[im][in_], av[im].x, av[im].y, av[im].z, av[im].w,
                        bv[in_].x, bv[in_].y);
    }
    CP_WAIT0();

    const int bm = blockIdx.y * 128, bn = blockIdx.x * 256;
    const int wm = wmHalf * 64, wn = wq * 64;
    const float qscale = 0.08838834764831845f;

#pragma unroll
    for (int im = 0; im < 4; im++) {
        const int row0 = bm + wm + im * 16 + tr;
        const int bIdx = row0 >> 11, s = row0 & 2047;
#pragma unroll
        for (int in_ = 0; in_ < 8; in_++) {
            const int col = bn + wn + in_ * 8 + 2 * tq;
            float c0 = acc[im][in_][0], c1 = acc[im][in_][1];
            float c2 = acc[im][in_][2], c3 = acc[im][in_][3];
            if (EPI == 0) {
                float* C = (float*)out0;
                *(float2*)(C + (size_t)row0 * DIM_ + col) = make_float2(c0, c1);
                *(float2*)(C + (size_t)(row0 + 8) * DIM_ + col) = make_float2(c2, c3);
            } else {
                if (col < 2048) {
                    // ---- Q: rope + scale -> A-frag words ----
                    const int hh = col >> 7, d = col & 127;
                    const int i = d >> 1;
                    const float cA = fcos[s * 64 + i], sA = fsin[s * 64 + i];
                    const float cB = fcos[(s + 8) * 64 + i], sB = fsin[(s + 8) * 64 + i];
                    const float r0 = (c0 * cA - c1 * sA) * qscale;
                    const float i0 = (c0 * sA + c1 * cA) * qscale;
                    const float r1 = (c2 * cB - c3 * sB) * qscale;
                    const float i1 = (c2 * sB + c3 * cB) * qscale;
                    const int qtile = s >> 7, srow = s & 127;
                    const int watt = srow >> 4;
                    const int gk = d >> 4, ksel = (d >> 3) & 1;
                    uint32_t* Qo = (uint32_t*)out0;
                    const size_t base =
                        ((((size_t)bIdx * 16 + qtile) * 16 + hh) * 8 + watt) * 1024 +
                        gk * 128 + (tr * 4 + tq) * 4 + 2 * ksel;
                    *(uint2*)(Qo + base) = make_uint2(h2pack(r0, i0), h2pack(r1, i1));
                } else if (col < 2560) {
                    // ---- K: rope -> B-frag words ----
                    const int ck = col - 2048;
                    const int g = ck >> 7, d = ck & 127;
                    const int i = d >> 1;
                    const float cA = fcos[s * 64 + i], sA = fsin[s * 64 + i];
                    const float cB = fcos[(s + 8) * 64 + i], sB = fsin[(s + 8) * 64 + i];
                    const float r0 = c0 * cA - c1 * sA, i0 = c0 * sA + c1 * cA;
                    const float r1 = c2 * cB - c3 * sB, i1 = c2 * sB + c3 * cB;
                    const int keytile = s >> 7, kl = s & 127;
                    const int in_a = kl >> 3, tr2 = kl & 7;
                    const int dch = d >> 4, rr = (d >> 3) & 1, tq2 = (d & 7) >> 1;
                    uint32_t* Ko = (uint32_t*)out1;
                    const size_t base =
                        (((size_t)(bIdx * 4 + g) * 16 + keytile) * 8 + dch) * 1024 +
                        in_a * 64 + (tr2 * 4 + tq2) * 2 + rr;
                    Ko[base] = h2pack(r0, i0);
                    Ko[base + 64] = h2pack(r1, i1);
                } else {
                    // ---- V: B-frag halves (key = s / s+8) ----
                    const int cv = col - 2560;
                    const int g = cv >> 7, d = cv & 127;
                    const int in_v = d >> 3, trv = d & 7;
                    const int kch = s >> 4, klo = s & 15;  // klo = tr < 8
                    const int tq2 = klo >> 1, half = klo & 1;
                    const size_t w0 =
                        (((size_t)(bIdx * 4 + g) * 128 + kch) * 16 + in_v) * 64 +
                        (trv * 4 + tq2) * 2;
                    __half* vh = (__half*)out2;
                    vh[2 * w0 + half] = __float2half(c0);
                    vh[2 * (w0 + 8) + half] = __float2half(c1);
                    vh[2 * (w0 + 1) + half] = __float2half(c2);
                    vh[2 * (w0 + 9) + half] = __float2half(c3);
                }
            }
        }
    }
}

// ---------------- fp16 flash attention v4: packed frags, KT=128 ----------------
#define QT 128
#define KT 128
#define KVSTG 16384                         // words/stage: K 8192 + V 8192
#define ATTN_SMEM_BYTES (2 * KVSTG * 4)     // 128 KB

__global__ __launch_bounds__(256, 1) void attn_h2(const uint32_t* __restrict__ Qf,
                                                  const uint32_t* __restrict__ Kf,
                                                  const uint32_t* __restrict__ Vf,
                                                  uint32_t* __restrict__ Opack) {
    extern __shared__ uint32_t smw[];
    const uint32_t smbase = smem_u32(smw);
    const int tid = threadIdx.x;
    const int w = tid >> 5, lane = tid & 31;
    const int tr = lane >> 2, tq = lane & 3;
    const int b = blockIdx.z, h = blockIdx.y;
    const int g = h / (NHEADS_ / NKV_);
    const int qb = (int)gridDim.x - 1 - (int)blockIdx.x;
    const int q0 = qb * QT;
    const int wm = w * 16;

    // ---- Q fragments straight from gmem (coalesced LDG.128) ----
    uint4 qa[8];
    {
        const uint32_t* qp = Qf + ((((size_t)b * 16 + qb) * 16 + h) * 8 + w) * 1024 + lane * 4;
#pragma unroll
        for (int gk = 0; gk < 8; gk++) qa[gk] = *(const uint4*)(qp + gk * 128);
    }

    const uint32_t* kg = Kf + ((size_t)(b * NKV_ + g) * 16) * 8192;   // per keytile 8192 words
    const uint32_t* vg = Vf + ((size_t)(b * NKV_ + g) * 128) * 1024;  // per kchunk 1024 words

    const int nchunk = qb + 1;

    // ---- prologue: stage chunk 0 (linear 64 KB) ----
#pragma unroll
    for (int j = 0; j < 8; j++) {
        const int o4 = (tid + 256 * j) * 4;
        cp_async16(smbase + o4 * 4, kg + o4);
        cp_async16(smbase + (8192 + o4) * 4, vg + o4);
    }
    CP_COMMIT();

    float m0 = -1e30f, m1 = -1e30f, l0 = 0.f, l1 = 0.f;
    float o[16][4];
#pragma unroll
    for (int j = 0; j < 16; j++)
#pragma unroll
        for (int r = 0; r < 4; r++) o[j][r] = 0.f;

    for (int kb = 0; kb < nchunk; kb++) {
        CP_WAIT0();
        __syncthreads();

        if (kb + 1 < nchunk) {
            const uint32_t sb = smbase + ((kb + 1) & 1) * KVSTG * 4;
            const uint32_t* kn = kg + (size_t)(kb + 1) * 8192;
            const uint32_t* vn = vg + (size_t)(kb + 1) * 8192;
#pragma unroll
            for (int j = 0; j < 8; j++) {
                const int o4 = (tid + 256 * j) * 4;
                cp_async16(sb + o4 * 4, kn + o4);
                cp_async16(sb + (8192 + o4) * 4, vn + o4);
            }
        }
        CP_COMMIT();

        const uint32_t* Ks = smw + (kb & 1) * KVSTG;
        const uint32_t* Vs = Ks + 8192;

        // ---- S = Q K^T : 128 rows x 128 keys per warp-row-slice ----
        float s[16][4];
#pragma unroll
        for (int in_ = 0; in_ < 16; in_++)
#pragma unroll
            for (int r = 0; r < 4; r++) s[in_][r] = 0.f;

#pragma unroll
        for (int gk = 0; gk < 8; gk++) {
            const uint32_t* kc = Ks + gk * 1024 + lane * 2;
#pragma unroll
            for (int in_ = 0; in_ < 16; in_++) {
                const uint2 kv = *(const uint2*)(kc + in_ * 64);
                mma_h16(s[in_], qa[gk].x, qa[gk].y, qa[gk].z, qa[gk].w, kv.x, kv.y);
            }
        }

        if (kb == qb) {
            const int key0 = kb * KT;
            const int r0 = q0 + wm + tr, r1 = r0 + 8;
#pragma unroll
            for (int in_ = 0; in_ < 16; in_++) {
                const int c = key0 + in_ * 8 + 2 * tq;
                if (c > r0) s[in_][0] = -1e30f;
                if (c + 1 > r0) s[in_][1] = -1e30f;
                if (c > r1) s[in_][2] = -1e30f;
                if (c + 1 > r1) s[in_][3] = -1e30f;
            }
        }

        // ---- online softmax ----
        float mx0 = -1e30f, mx1 = -1e30f;
#pragma unroll
        for (int in_ = 0; in_ < 16; in_++) {
            mx0 = fmaxf(mx0, fmaxf(s[in_][0], s[in_][1]));
            mx1 = fmaxf(mx1, fmaxf(s[in_][2], s[in_][3]));
        }
        mx0 = fmaxf(mx0, __shfl_xor_sync(0xffffffffu, mx0, 1));
        mx0 = fmaxf(mx0, __shfl_xor_sync(0xffffffffu, mx0, 2));
        mx1 = fmaxf(mx1, __shfl_xor_sync(0xffffffffu, mx1, 1));
        mx1 = fmaxf(mx1, __shfl_xor_sync(0xffffffffu, mx1, 2));

        const float nm0 = fmaxf(m0, mx0), nm1 = fmaxf(m1, mx1);
        const float al0 = __expf(m0 - nm0), al1 = __expf(m1 - nm1);
        float sum0 = 0.f, sum1 = 0.f;
#pragma unroll
        for (int in_ = 0; in_ < 16; in_++) {
            s[in_][0] = __expf(s[in_][0] - nm0);
            s[in_][1] = __expf(s[in_][1] - nm0);
            s[in_][2] = __expf(s[in_][2] - nm1);
            s[in_][3] = __expf(s[in_][3] - nm1);
            sum0 += s[in_][0] + s[in_][1];
            sum1 += s[in_][2] + s[in_][3];
        }
        sum0 += __shfl_xor_sync(0xffffffffu, sum0, 1);
        sum0 += __shfl_xor_sync(0xffffffffu, sum0, 2);
        sum1 += __shfl_xor_sync(0xffffffffu, sum1, 1);
        sum1 += __shfl_xor_sync(0xffffffffu, sum1, 2);
        l0 = l0 * al0 + sum0;
        l1 = l1 * al1 + sum1;
        m0 = nm0; m1 = nm1;

#pragma unroll
        for (int j = 0; j < 16; j++) {
            o[j][0] *= al0; o[j][1] *= al0;
            o[j][2] *= al1; o[j][3] *= al1;
        }

        // ---- pack P into A-fragments (registers only) ----
        uint4 pa[8];
#pragma unroll
        for (int gp = 0; gp < 8; gp++) {
            pa[gp].x = h2pack(s[2 * gp][0], s[2 * gp][1]);
            pa[gp].y = h2pack(s[2 * gp][2], s[2 * gp][3]);
            pa[gp].z = h2pack(s[2 * gp + 1][0], s[2 * gp + 1][1]);
            pa[gp].w = h2pack(s[2 * gp + 1][2], s[2 * gp + 1][3]);
        }

        // ---- O += P V ----
#pragma unroll
        for (int gp = 0; gp < 8; gp++) {
            const uint32_t* vc = Vs + gp * 1024 + lane * 2;
#pragma unroll
            for (int j = 0; j < 16; j++) {
                const uint2 vv = *(const uint2*)(vc + j * 64);
                mma_h16(o[j], pa[gp].x, pa[gp].y, pa[gp].z, pa[gp].w, vv.x, vv.y);
            }
        }
    }

    // ---- epilogue: packed A-fragments for O-projection ----
    const float inv0 = 1.f / l0, inv1 = 1.f / l1;
    const int mtile = b * (SEQ_ / 128) + qb;
    const int wmHalf = w >> 2, im = w & 3;
#pragma unroll
    for (int jp = 0; jp < 8; jp++) {
        const int j0 = 2 * jp, j1 = 2 * jp + 1;
        uint4 ov;
        ov.x = h2pack(o[j0][0] * inv0, o[j0][1] * inv0);
        ov.y = h2pack(o[j0][2] * inv1, o[j0][3] * inv1);
        ov.z = h2pack(o[j1][0] * inv0, o[j1][1] * inv0);
        ov.w = h2pack(o[j1][2] * inv1, o[j1][3] * inv1);
        uint32_t* dst = Opack + ((size_t)mtile * (DIM_ / 16) + h * 8 + jp) * 1024 +
                        wmHalf * 512 + im * 128 + lane * 4;
        *(uint4*)dst = ov;
    }
}

// ---------------- launch ----------------
extern "C" void kernel_launch(void* const* d_in, const int* in_sizes, int n_in,
                              void* d_out, int out_size) {
    const float* x = (const float*)d_in[0];
    const float* fcos = (const float*)d_in[1];
    const float* fsin = (const float*)d_in[2];
    const float* Wq = (const float*)d_in[3];
    const float* Wk = (const float*)d_in[4];
    const float* Wv = (const float*)d_in[5];
    const float* Wo = (const float*)d_in[6];
    float* out = (float*)d_out;

    void *qp, *kp, *vp, *ap, *xp, *wcomb, *wo;
    cudaGetSymbolAddress(&qp, g_q);
    cudaGetSymbolAddress(&kp, g_k);
    cudaGetSymbolAddress(&vp, g_v);
    cudaGetSymbolAddress(&ap, g_attn);
    cudaGetSymbolAddress(&xp, g_x32);
    cudaGetSymbolAddress(&wcomb, g_wqT);
    cudaGetSymbolAddress(&wo, g_woT);

    cudaFuncSetAttribute(attn_h2, cudaFuncAttributeMaxDynamicSharedMemorySize, ATTN_SMEM_BYTES);

    // prepass: pack x; pack Wq/Wk/Wv into combined B buffer (nblks 0-7, 8-9, 10-11); Wo
    repack_A_h<<<dim3(DIM_ / 16, M_ / 128), 256>>>(x, (uint32_t*)xp, DIM_);
    repack_B2<<<dim3(128, 8), 256>>>(Wq, (uint32_t*)wcomb, DIM_, 0);
    repack_B2<<<dim3(128, 2), 256>>>(Wk, (uint32_t*)wcomb, NKV_ * HD_, 8);
    repack_B2<<<dim3(128, 2), 256>>>(Wv, (uint32_t*)wcomb, NKV_ * HD_, 10);
    repack_B2<<<dim3(128, 8), 256>>>(Wo, (uint32_t*)wo, DIM_, 0);

    // fused QKV projection (N = 3072): Q frags / K frags / V frags
    gemm_h2<5><<<dim3(12, M_ / 128), 256>>>(
        (const uint32_t*)xp, (const uint32_t*)wcomb, qp, kp, vp, fcos, fsin);

    // attention
    {
        dim3 grid(SEQ_ / QT, NHEADS_, BATCH_);
        attn_h2<<<grid, 256, ATTN_SMEM_BYTES>>>((const uint32_t*)qp, (const uint32_t*)kp,
                                                (const uint32_t*)vp, (uint32_t*)ap);
    }

    // output projection (fp32 out)
    gemm_h2<0><<<dim3(8, M_ / 128), 256>>>(
        (const uint32_t*)ap, (const uint32_t*)wo, out, nullptr, nullptr, nullptr, nullptr);
}